// round 8
// baseline (speedup 1.0000x reference)
#include <cuda_runtime.h>
#include <cuda_fp16.h>

#define N_NODES 100000
#define N_EDGES 1600000
#define N_GRAPH 1024
#define EMB 32
#define DC 128
#define WPB 8       // warps per block
#define NPW 8       // nodes per warp (register blocking in dense kernels)
#define NTPB 256

// ---------------- scratch (static device globals; no allocation) ----------------
__device__ int    g_deg[N_NODES];        // zeroed by k_pool of previous run (init: BSS zero)
__device__ int    g_rowptr[N_NODES + 1];
__device__ int    g_cursor[N_NODES];
__device__ int    g_col[N_EDGES];
__device__ int    g_bsums[256];
__device__ int    g_gdeg[N_GRAPH];       // zeroed by k_pool of previous run
__device__ int    g_gptr[N_GRAPH + 1];
__device__ __half g_xwh[(size_t)N_NODES * DC];   // fp16 message payload
__device__ float  g_h1[(size_t)N_NODES * DC];
__device__ float  g_als[N_NODES * 2];
__device__ float  g_ald[N_NODES * 2];
__device__ uint4  g_pk[N_EDGES];         // packed per-edge {src, exp0, exp1, _}
__device__ float  g_gate[N_NODES];

__device__ __forceinline__ float lrelu(float x, float s) { return x > 0.f ? x : s * x; }

// f32x2 packed helpers (sm_103a; ptxas never emits FFMA2 from C++)
__device__ __forceinline__ unsigned long long pack2(float v) {
    unsigned long long r; asm("mov.b64 %0,{%1,%1};" : "=l"(r) : "f"(v)); return r;
}
__device__ __forceinline__ void fma2(unsigned long long& a, unsigned long long x, unsigned long long p) {
    asm("fma.rn.f32x2 %0,%1,%2,%0;" : "+l"(a) : "l"(x), "l"(p));
}
__device__ __forceinline__ float2 unpack2(unsigned long long v) {
    float2 r; asm("mov.b64 {%0,%1},%2;" : "=f"(r.x), "=f"(r.y) : "l"(v)); return r;
}

// store 4 fp32 as 4 fp16 in one 8B write
__device__ __forceinline__ void store_h4(__half* row, int lane, float a, float b, float c, float d) {
    union { uint2 u; __half2 h[2]; } cv;
    cv.h[0] = __float22half2_rn(make_float2(a, b));
    cv.h[1] = __float22half2_rn(make_float2(c, d));
    ((uint2*)row)[lane] = cv.u;
}

// 8 halfs (uint4) * p accumulated into 8 fp32
__device__ __forceinline__ void h8_fma(float* acc, uint4 v, float p) {
    union { unsigned u; __half2 h; } c;
    float2 f;
    c.u = v.x; f = __half22float2(c.h); acc[0] += f.x * p; acc[1] += f.y * p;
    c.u = v.y; f = __half22float2(c.h); acc[2] += f.x * p; acc[3] += f.y * p;
    c.u = v.z; f = __half22float2(c.h); acc[4] += f.x * p; acc[5] += f.y * p;
    c.u = v.w; f = __half22float2(c.h); acc[6] += f.x * p; acc[7] += f.y * p;
}

// ---------------- CSR build ----------------
__global__ void k_hist(const int* __restrict__ ei, const int* __restrict__ batch) {
    int i = blockIdx.x * blockDim.x + threadIdx.x;
    if (i < N_EDGES) atomicAdd(&g_deg[ei[N_EDGES + i]], 1);
    if (i < N_NODES) atomicAdd(&g_gdeg[batch[i]], 1);
}

__global__ void k_scan_block() {
    __shared__ int sh[1024];
    int t = threadIdx.x;
    int i = blockIdx.x * 1024 + t;
    int v = (i < N_NODES) ? g_deg[i] : 0;
    sh[t] = v;
    __syncthreads();
    for (int off = 1; off < 1024; off <<= 1) {
        int a = (t >= off) ? sh[t - off] : 0;
        __syncthreads();
        sh[t] += a;
        __syncthreads();
    }
    if (i < N_NODES) g_rowptr[i] = sh[t] - v;
    if (t == 1023) g_bsums[blockIdx.x] = sh[1023];
}

// fused: block-sum scan + add + cursor init + total; last block also builds g_gptr
__global__ void k_scan_add2(int nb) {
    __shared__ int sb[128];
    int t = threadIdx.x;
    if (t < 128) sb[t] = (t < nb) ? g_bsums[t] : 0;
    __syncthreads();
    for (int off = 1; off < 128; off <<= 1) {
        int a = (t < 128 && t >= off) ? sb[t - off] : 0;
        __syncthreads();
        if (t < 128) sb[t] += a;
        __syncthreads();
    }
    int i = blockIdx.x * blockDim.x + t;
    if (i < N_NODES) {
        int b = i >> 10;
        int vv = g_rowptr[i] + (b ? sb[b - 1] : 0);
        g_rowptr[i] = vv;
        g_cursor[i] = vv;
    }
    if (i == 0) g_rowptr[N_NODES] = sb[nb - 1];

    if (blockIdx.x == gridDim.x - 1) {    // graph-pointer scan (1024 entries, 4/thread)
        __shared__ int gs[256];
        int b4 = t * 4;
        int a0 = g_gdeg[b4], a1 = g_gdeg[b4 + 1], a2 = g_gdeg[b4 + 2], a3 = g_gdeg[b4 + 3];
        int tot = a0 + a1 + a2 + a3;
        gs[t] = tot;
        __syncthreads();
        for (int off = 1; off < 256; off <<= 1) {
            int a = (t >= off) ? gs[t - off] : 0;
            __syncthreads();
            gs[t] += a;
            __syncthreads();
        }
        int excl = gs[t] - tot;
        g_gptr[b4]     = excl;
        g_gptr[b4 + 1] = excl + a0;
        g_gptr[b4 + 2] = excl + a0 + a1;
        g_gptr[b4 + 3] = excl + a0 + a1 + a2;
        if (t == 255) g_gptr[N_GRAPH] = gs[255];
    }
}

__global__ void k_scatter(const int* __restrict__ ei) {
    int i = blockIdx.x * blockDim.x + threadIdx.x;
    if (i >= N_EDGES) return;
    int s = ei[i];
    int d = ei[N_EDGES + i];
    int pos = atomicAdd(&g_cursor[d], 1);
    g_col[pos] = s;
}

// warp-per-node sort: shfl bitonic (L<=32 and L<=64 paths), smem fallback
__global__ void k_rowsortw() {
    __shared__ int buf[WPB][160];
    int wl = threadIdx.x >> 5, lane = threadIdx.x & 31;
    int n = blockIdx.x * WPB + wl;
    if (n >= N_NODES) return;
    int rs = g_rowptr[n], L = g_rowptr[n + 1] - rs;
    if (L <= 1) return;
    if (L <= 32) {
        int v = (lane < L) ? g_col[rs + lane] : 0x7fffffff;
#pragma unroll
        for (int k = 2; k <= 32; k <<= 1) {
#pragma unroll
            for (int j = k >> 1; j; j >>= 1) {
                int o = __shfl_xor_sync(~0u, v, j);
                bool up = ((lane & k) == 0);
                bool lo = ((lane & j) == 0);
                v = (up == lo) ? min(v, o) : max(v, o);
            }
        }
        if (lane < L) g_col[rs + lane] = v;
    } else if (L <= 64) {
        int i0 = lane, i1 = lane + 32;
        int v0 = (i0 < L) ? g_col[rs + i0] : 0x7fffffff;
        int v1 = (i1 < L) ? g_col[rs + i1] : 0x7fffffff;
#pragma unroll
        for (int k = 2; k <= 64; k <<= 1) {
#pragma unroll
            for (int j = k >> 1; j; j >>= 1) {
                if (j >= 32) {
                    int lo = min(v0, v1), hi = max(v0, v1);
                    v0 = lo; v1 = hi;
                } else {
                    int o0 = __shfl_xor_sync(~0u, v0, j);
                    int o1 = __shfl_xor_sync(~0u, v1, j);
                    bool up0 = ((i0 & k) == 0), up1 = ((i1 & k) == 0);
                    bool lo0 = ((i0 & j) == 0), lo1 = ((i1 & j) == 0);
                    v0 = (up0 == lo0) ? min(v0, o0) : max(v0, o0);
                    v1 = (up1 == lo1) ? min(v1, o1) : max(v1, o1);
                }
            }
        }
        if (i0 < L) g_col[rs + i0] = v0;
        if (i1 < L) g_col[rs + i1] = v1;
    } else if (L <= 160) {
        for (int i = lane; i < L; i += 32) buf[wl][i] = g_col[rs + i];
        __syncwarp();
        for (int p = 0; p < L; p++) {
            for (int i = (p & 1) + 2 * lane; i + 1 < L; i += 64) {
                int a = buf[wl][i], b = buf[wl][i + 1];
                if (a > b) { buf[wl][i] = b; buf[wl][i + 1] = a; }
            }
            __syncwarp();
        }
        for (int i = lane; i < L; i += 32) g_col[rs + i] = buf[wl][i];
    } else if (lane == 0) {
        int re = rs + L;
        for (int i = rs + 1; i < re; i++) {
            int key = g_col[i];
            int j = i - 1;
            while (j >= rs && g_col[j] > key) { g_col[j + 1] = g_col[j]; j--; }
            g_col[j + 1] = key;
        }
    }
}

// ---------------- layer 1: embed + LN + W1 + logits (8 nodes/warp, f32x2) ----------------
__global__ void k_node1(const int* __restrict__ x, const float* __restrict__ emb,
                        const float* __restrict__ lng, const float* __restrict__ lnb,
                        const float* __restrict__ W1, const float* __restrict__ asr,
                        const float* __restrict__ adt) {
    __shared__ ulonglong2 sW[EMB * 32];
    __shared__ float sxn[WPB][NPW][EMB];
    int tid = threadIdx.x;
    int wl = tid >> 5, lane = tid & 31;
    {
        const ulonglong2* W4 = (const ulonglong2*)W1;
        for (int i = tid; i < EMB * 32; i += NTPB) sW[i] = W4[i];
    }
    int nbase = (blockIdx.x * WPB + wl) * NPW;

#pragma unroll
    for (int j = 0; j < NPW; j++) {
        int n = nbase + j;
        float xn = 0.f;
        if (n < N_NODES) {
            int vi = x[n];
            float xv = emb[vi * EMB + lane];
            float m = xv;
            for (int o = 16; o; o >>= 1) m += __shfl_xor_sync(~0u, m, o);
            m *= (1.f / EMB);
            float dv = xv - m;
            float var = dv * dv;
            for (int o = 16; o; o >>= 1) var += __shfl_xor_sync(~0u, var, o);
            var *= (1.f / EMB);
            xn = dv * rsqrtf(var + 1e-5f) * lng[lane] + lnb[lane];
        }
        sxn[wl][j][lane] = xn;
    }
    __syncthreads();

    unsigned long long accA[NPW], accB[NPW];
#pragma unroll
    for (int j = 0; j < NPW; j++) { accA[j] = 0ull; accB[j] = 0ull; }
#pragma unroll
    for (int k = 0; k < EMB; k += 4) {
        ulonglong2 w0 = sW[(k + 0) * 32 + lane];
        ulonglong2 w1 = sW[(k + 1) * 32 + lane];
        ulonglong2 w2 = sW[(k + 2) * 32 + lane];
        ulonglong2 w3 = sW[(k + 3) * 32 + lane];
#pragma unroll
        for (int j = 0; j < NPW; j++) {
            float4 h4 = *(const float4*)&sxn[wl][j][k];
            unsigned long long p;
            p = pack2(h4.x); fma2(accA[j], w0.x, p); fma2(accB[j], w0.y, p);
            p = pack2(h4.y); fma2(accA[j], w1.x, p); fma2(accB[j], w1.y, p);
            p = pack2(h4.z); fma2(accA[j], w2.x, p); fma2(accB[j], w2.y, p);
            p = pack2(h4.w); fma2(accA[j], w3.x, p); fma2(accB[j], w3.y, p);
        }
    }

    float4 as4 = __ldg((const float4*)asr + lane);
    float4 ad4 = __ldg((const float4*)adt + lane);
#pragma unroll
    for (int j = 0; j < NPW; j++) {
        int n = nbase + j;
        float2 lo = unpack2(accA[j]), hi = unpack2(accB[j]);
        float ps = lo.x * as4.x + lo.y * as4.y + hi.x * as4.z + hi.y * as4.w;
        float pd = lo.x * ad4.x + lo.y * ad4.y + hi.x * ad4.z + hi.y * ad4.w;
        for (int o = 8; o; o >>= 1) {
            ps += __shfl_xor_sync(~0u, ps, o);
            pd += __shfl_xor_sync(~0u, pd, o);
        }
        if (n < N_NODES) {
            store_h4(g_xwh + (size_t)n * DC, lane, lo.x, lo.y, hi.x, hi.y);
            if ((lane & 15) == 0) {
                int h = lane >> 4;
                g_als[n * 2 + h] = ps;
                g_ald[n * 2 + h] = pd;
            }
        }
    }
}

// ---------------- GAT aggregation: warp/node; fused logit+exp+pack pass, then gather ----------------
__global__ void k_agg(const float* __restrict__ bias, float* __restrict__ out2, int layer) {
    int n = blockIdx.x * WPB + (threadIdx.x >> 5);
    int lane = threadIdx.x & 31;
    if (n >= N_NODES) return;

    int rs = g_rowptr[n], re = g_rowptr[n + 1];
    float2 a = *(const float2*)&g_als[2 * n];
    float2 b = *(const float2*)&g_ald[2 * n];
    float ps0 = __expf(lrelu(a.x + b.x, 0.2f));
    float ps1 = __expf(lrelu(a.y + b.y, 0.2f));

    // pass 1 (fused elog): gather src logits, exp, pack {src,exp0,exp1}, accumulate sums
    float s0 = 0.f, s1 = 0.f;
    for (int k = rs + lane; k < re; k += 32) {
        int src = __ldg(g_col + k);
        float2 av = __ldg((const float2*)g_als + src);
        float p0 = __expf(lrelu(av.x + b.x, 0.2f));
        float p1 = __expf(lrelu(av.y + b.y, 0.2f));
        s0 += p0;
        s1 += p1;
        uint4 rec;
        rec.x = (unsigned)src;
        rec.y = __float_as_uint(p0);
        rec.z = __float_as_uint(p1);
        rec.w = 0;
        g_pk[k] = rec;
    }
#pragma unroll
    for (int o = 16; o; o >>= 1) {
        s0 += __shfl_xor_sync(~0u, s0, o);
        s1 += __shfl_xor_sync(~0u, s1, o);
    }
    float inv0 = 1.f / (s0 + ps0);
    float inv1 = 1.f / (s1 + ps1);

    int half  = lane >> 4;   // edge slot within iteration
    int s16   = lane & 15;   // feature chunk: 8 halfs [8*s16, 8*s16+8)
    int headb = s16 >> 3;    // head owning my dims

    // pass 2: weighted gather, 2 edges per warp iteration, uint4 (8 halfs) per lane
    float acc[8];
    {
        float pself = (half == 0) ? (headb ? ps1 : ps0) : 0.f;
        uint4 xs = __ldg((const uint4*)(g_xwh + (size_t)n * DC) + s16);
#pragma unroll
        for (int i = 0; i < 8; i++) acc[i] = 0.f;
        h8_fma(acc, xs, pself);
    }
#pragma unroll 4
    for (int k = rs; k < re; k += 2) {
        int kk = k + half;
        int kc = kk < re ? kk : re - 1;
        uint4 rec = __ldg(g_pk + kc);           // one broadcast LDG.128 per edge
        int src = (int)rec.x;
        float p = (kk < re) ? __uint_as_float(headb ? rec.z : rec.y) : 0.f;
        uint4 xv = __ldg((const uint4*)(g_xwh + (size_t)src * DC) + s16);
        h8_fma(acc, xv, p);
    }
#pragma unroll
    for (int i = 0; i < 8; i++) acc[i] += __shfl_xor_sync(~0u, acc[i], 16);

    float invh = headb ? inv1 : inv0;
    int idx = s16 * 2 + half;
    float4 bi = __ldg((const float4*)bias + idx);
    const float* ap = acc + half * 4;
    float4 o;
    o.x = ap[0] * invh + bi.x;
    o.y = ap[1] * invh + bi.y;
    o.z = ap[2] * invh + bi.z;
    o.w = ap[3] * invh + bi.w;
    if (layer == 1) {
        o.x = lrelu(o.x, 0.05f); o.y = lrelu(o.y, 0.05f);
        o.z = lrelu(o.z, 0.05f); o.w = lrelu(o.w, 0.05f);
        ((float4*)g_h1)[(size_t)n * 32 + idx] = o;
    } else {
        ((float4*)out2)[(size_t)n * 32 + idx] = o;
    }
}

// ---------------- layer 2 node transform: h1 @ W2 + logits (8 nodes/warp, smem W2) ----------------
__global__ void k_node2(const float* __restrict__ W2, const float* __restrict__ asr,
                        const float* __restrict__ adt) {
    extern __shared__ float dsm[];
    ulonglong2* sW = (ulonglong2*)dsm;                 // 64KB
    float* sh = dsm + DC * DC;                         // 16KB
    int tid = threadIdx.x;
    int wl = tid >> 5, lane = tid & 31;
    {
        const ulonglong2* W4 = (const ulonglong2*)W2;
        for (int i = tid; i < DC * 32; i += NTPB) sW[i] = W4[i];
    }
    int nbase = (blockIdx.x * WPB + wl) * NPW;
    float* shw = sh + (size_t)wl * NPW * DC;
#pragma unroll
    for (int j = 0; j < NPW; j++) {
        int n = nbase + j;
        float4 v = (n < N_NODES) ? ((const float4*)g_h1)[(size_t)n * 32 + lane]
                                 : make_float4(0.f, 0.f, 0.f, 0.f);
        *(float4*)&shw[j * DC + lane * 4] = v;
    }
    __syncthreads();

    unsigned long long accA[NPW], accB[NPW];
#pragma unroll
    for (int j = 0; j < NPW; j++) { accA[j] = 0ull; accB[j] = 0ull; }
    for (int k = 0; k < DC; k += 4) {
        ulonglong2 w0 = sW[(k + 0) * 32 + lane];
        ulonglong2 w1 = sW[(k + 1) * 32 + lane];
        ulonglong2 w2 = sW[(k + 2) * 32 + lane];
        ulonglong2 w3 = sW[(k + 3) * 32 + lane];
#pragma unroll
        for (int j = 0; j < NPW; j++) {
            float4 h4 = *(const float4*)&shw[j * DC + k];
            unsigned long long p;
            p = pack2(h4.x); fma2(accA[j], w0.x, p); fma2(accB[j], w0.y, p);
            p = pack2(h4.y); fma2(accA[j], w1.x, p); fma2(accB[j], w1.y, p);
            p = pack2(h4.z); fma2(accA[j], w2.x, p); fma2(accB[j], w2.y, p);
            p = pack2(h4.w); fma2(accA[j], w3.x, p); fma2(accB[j], w3.y, p);
        }
    }

    float4 as4 = __ldg((const float4*)asr + lane);
    float4 ad4 = __ldg((const float4*)adt + lane);
#pragma unroll
    for (int j = 0; j < NPW; j++) {
        int n = nbase + j;
        float2 lo = unpack2(accA[j]), hi = unpack2(accB[j]);
        float ps = lo.x * as4.x + lo.y * as4.y + hi.x * as4.z + hi.y * as4.w;
        float pd = lo.x * ad4.x + lo.y * ad4.y + hi.x * ad4.z + hi.y * ad4.w;
        for (int o = 8; o; o >>= 1) {
            ps += __shfl_xor_sync(~0u, ps, o);
            pd += __shfl_xor_sync(~0u, pd, o);
        }
        if (n < N_NODES) {
            store_h4(g_xwh + (size_t)n * DC, lane, lo.x, lo.y, hi.x, hi.y);
            if ((lane & 15) == 0) {
                int h = lane >> 4;
                g_als[n * 2 + h] = ps;
                g_ald[n * 2 + h] = pd;
            }
        }
    }
}

// ---------------- gate MLP (8 nodes/warp, smem gw1) ----------------
__global__ void k_gate(const float* __restrict__ hout, const float* __restrict__ gw1,
                       const float* __restrict__ gb1, const float* __restrict__ gw2,
                       const float* __restrict__ gb2) {
    extern __shared__ float dsm[];
    unsigned long long* sg = (unsigned long long*)dsm;   // 32KB
    float* sh = dsm + DC * 64;                           // 16KB
    int tid = threadIdx.x;
    int wl = tid >> 5, lane = tid & 31;
    {
        const unsigned long long* G = (const unsigned long long*)gw1;
        for (int i = tid; i < DC * 32; i += NTPB) sg[i] = G[i];
    }
    int nbase = (blockIdx.x * WPB + wl) * NPW;
    float* shw = sh + (size_t)wl * NPW * DC;
#pragma unroll
    for (int j = 0; j < NPW; j++) {
        int n = nbase + j;
        float4 v = (n < N_NODES) ? ((const float4*)hout)[(size_t)n * 32 + lane]
                                 : make_float4(0.f, 0.f, 0.f, 0.f);
        *(float4*)&shw[j * DC + lane * 4] = v;
    }
    __syncthreads();

    unsigned long long acc[NPW];
#pragma unroll
    for (int j = 0; j < NPW; j++) acc[j] = 0ull;
    for (int k = 0; k < DC; k += 4) {
        unsigned long long w0 = sg[(k + 0) * 32 + lane];
        unsigned long long w1 = sg[(k + 1) * 32 + lane];
        unsigned long long w2 = sg[(k + 2) * 32 + lane];
        unsigned long long w3 = sg[(k + 3) * 32 + lane];
#pragma unroll
        for (int j = 0; j < NPW; j++) {
            float4 h4 = *(const float4*)&shw[j * DC + k];
            fma2(acc[j], w0, pack2(h4.x));
            fma2(acc[j], w1, pack2(h4.y));
            fma2(acc[j], w2, pack2(h4.z));
            fma2(acc[j], w3, pack2(h4.w));
        }
    }

    float2 gb = __ldg((const float2*)gb1 + lane);
    float2 g2 = __ldg((const float2*)gw2 + lane);
    float gbias = __ldg(gb2);
#pragma unroll
    for (int j = 0; j < NPW; j++) {
        float2 u = unpack2(acc[j]);
        u.x = lrelu(u.x + gb.x, 0.05f);
        u.y = lrelu(u.y + gb.y, 0.05f);
        float ps = u.x * g2.x + u.y * g2.y;
        for (int o = 16; o; o >>= 1) ps += __shfl_xor_sync(~0u, ps, o);
        int n = nbase + j;
        if (lane == 0 && n < N_NODES) g_gate[n] = ps + gbias;
    }
}

// ---------------- per-graph softmax pooling + scratch re-zero for next call ----------------
__global__ void k_pool(const float* __restrict__ hout, float* __restrict__ zout) {
    int g = blockIdx.x;
    int t = threadIdx.x;
    int s = g_gptr[g], e = g_gptr[g + 1];
    __shared__ float red[128];
    __shared__ float wbuf[128];

    float lm = -3.4e38f;
    for (int i = s + t; i < e; i += 128) lm = fmaxf(lm, g_gate[i]);
    red[t] = lm;
    __syncthreads();
    for (int o = 64; o; o >>= 1) { if (t < o) red[t] = fmaxf(red[t], red[t + o]); __syncthreads(); }
    float gm = red[0];
    __syncthreads();

    float ls = 0.f;
    for (int i = s + t; i < e; i += 128) ls += __expf(g_gate[i] - gm);
    red[t] = ls;
    __syncthreads();
    for (int o = 64; o; o >>= 1) { if (t < o) red[t] += red[t + o]; __syncthreads(); }
    float inv = (e > s) ? 1.f / red[0] : 0.f;
    __syncthreads();

    float acc = 0.f;
    for (int base = s; base < e; base += 128) {
        int i = base + t;
        wbuf[t] = (i < e) ? __expf(g_gate[i] - gm) * inv : 0.f;
        __syncthreads();
        int cnt = min(128, e - base);
#pragma unroll 4
        for (int j = 0; j < cnt; j++)
            acc += wbuf[j] * hout[(size_t)(base + j) * DC + t];
        __syncthreads();
    }
    zout[g * DC + t] = acc;

    // re-zero histogram scratch for the next kernel_launch call (1024*128 >= N_NODES)
    int gid = g * 128 + t;
    if (gid < N_NODES) g_deg[gid] = 0;
    if (gid < N_GRAPH) g_gdeg[gid] = 0;
}

// ---------------- launch ----------------
extern "C" void kernel_launch(void* const* d_in, const int* in_sizes, int n_in,
                              void* d_out, int out_size) {
    const int*   x     = (const int*)d_in[0];
    const int*   ei    = (const int*)d_in[1];
    const int*   batch = (const int*)d_in[2];
    const float* emb   = (const float*)d_in[3];
    const float* lng   = (const float*)d_in[4];
    const float* lnb   = (const float*)d_in[5];
    const float* W1    = (const float*)d_in[6];
    const float* as1   = (const float*)d_in[7];
    const float* ad1   = (const float*)d_in[8];
    const float* b1    = (const float*)d_in[9];
    const float* W2    = (const float*)d_in[10];
    const float* as2   = (const float*)d_in[11];
    const float* ad2   = (const float*)d_in[12];
    const float* b2    = (const float*)d_in[13];
    const float* gw1   = (const float*)d_in[14];
    const float* gb1   = (const float*)d_in[15];
    const float* gw2   = (const float*)d_in[16];
    const float* gb2   = (const float*)d_in[17];
    float* out  = (float*)d_out;
    float* zout = out + (size_t)N_NODES * DC;

    const int node2_smem = DC * DC * 4 + WPB * NPW * DC * 4;   // 80 KB
    const int gate_smem  = DC * 64 * 4 + WPB * NPW * DC * 4;   // 48 KB
    cudaFuncSetAttribute(k_node2, cudaFuncAttributeMaxDynamicSharedMemorySize, node2_smem);
    cudaFuncSetAttribute(k_gate,  cudaFuncAttributeMaxDynamicSharedMemorySize, gate_smem);

    int nb_scan = (N_NODES + 1023) / 1024;

    // CSR build + graph segment pointers (5 launches; g_deg/g_gdeg pre-zeroed by prior k_pool)
    k_hist<<<(N_EDGES + 255) / 256, 256>>>(ei, batch);
    k_scan_block<<<nb_scan, 1024>>>();
    k_scan_add2<<<(N_NODES + 255) / 256, 256>>>(nb_scan);
    k_scatter<<<(N_EDGES + 255) / 256, 256>>>(ei);
    k_rowsortw<<<(N_NODES + WPB - 1) / WPB, NTPB>>>();

    int nb_agg = (N_NODES + WPB - 1) / WPB;
    int nb_blk = (N_NODES + WPB * NPW - 1) / (WPB * NPW);

    k_node1<<<nb_blk, NTPB>>>(x, emb, lng, lnb, W1, as1, ad1);
    k_agg<<<nb_agg, NTPB>>>(b1, nullptr, 1);
    k_node2<<<nb_blk, NTPB, node2_smem>>>(W2, as2, ad2);
    k_agg<<<nb_agg, NTPB>>>(b2, out, 2);
    k_gate<<<nb_blk, NTPB, gate_smem>>>(out, gw1, gb1, gw2, gb2);
    k_pool<<<N_GRAPH, 128>>>(out, zout);
}

// round 10
// speedup vs baseline: 1.3435x; 1.3435x over previous
#include <cuda_runtime.h>
#include <cuda_fp16.h>

#define N_NODES 100000
#define N_EDGES 1600000
#define N_GRAPH 1024
#define EMB 32
#define DC 128
#define WPB 8       // warps per block
#define NPW 8       // nodes per warp (register blocking in dense kernels)
#define NTPB 256

// ---------------- scratch (static device globals; no allocation) ----------------
__device__ int    g_deg[N_NODES];        // zeroed by k_pool of previous run (init: BSS zero)
__device__ int    g_rowptr[N_NODES + 1];
__device__ int    g_cursor[N_NODES];
__device__ int2   g_sd[N_EDGES];         // {src, dst} per CSR slot
__device__ int    g_bsums[256];
__device__ int    g_gdeg[N_GRAPH];       // zeroed by k_pool of previous run
__device__ int    g_gptr[N_GRAPH + 1];
__device__ __half g_xwh[(size_t)N_NODES * DC];   // fp16 message payload
__device__ float  g_h1[(size_t)N_NODES * DC];
__device__ float  g_als[N_NODES * 2];
__device__ float  g_ald[N_NODES * 2];
__device__ float  g_elog[(size_t)N_EDGES * 2];
__device__ float  g_gate[N_NODES];

__device__ __forceinline__ float lrelu(float x, float s) { return x > 0.f ? x : s * x; }

// f32x2 packed helpers (sm_103a; ptxas never emits FFMA2 from C++)
__device__ __forceinline__ unsigned long long pack2(float v) {
    unsigned long long r; asm("mov.b64 %0,{%1,%1};" : "=l"(r) : "f"(v)); return r;
}
__device__ __forceinline__ void fma2(unsigned long long& a, unsigned long long x, unsigned long long p) {
    asm("fma.rn.f32x2 %0,%1,%2,%0;" : "+l"(a) : "l"(x), "l"(p));
}
__device__ __forceinline__ float2 unpack2(unsigned long long v) {
    float2 r; asm("mov.b64 {%0,%1},%2;" : "=f"(r.x), "=f"(r.y) : "l"(v)); return r;
}

// store 4 fp32 as 4 fp16 in one 8B write
__device__ __forceinline__ void store_h4(__half* row, int lane, float a, float b, float c, float d) {
    union { uint2 u; __half2 h[2]; } cv;
    cv.h[0] = __float22half2_rn(make_float2(a, b));
    cv.h[1] = __float22half2_rn(make_float2(c, d));
    ((uint2*)row)[lane] = cv.u;
}

// 8 halfs (uint4) * p accumulated into 8 fp32
__device__ __forceinline__ void h8_fma(float* acc, uint4 v, float p) {
    union { unsigned u; __half2 h; } c;
    float2 f;
    c.u = v.x; f = __half22float2(c.h); acc[0] += f.x * p; acc[1] += f.y * p;
    c.u = v.y; f = __half22float2(c.h); acc[2] += f.x * p; acc[3] += f.y * p;
    c.u = v.z; f = __half22float2(c.h); acc[4] += f.x * p; acc[5] += f.y * p;
    c.u = v.w; f = __half22float2(c.h); acc[6] += f.x * p; acc[7] += f.y * p;
}

// ---------------- CSR build ----------------
__global__ void k_hist(const int* __restrict__ ei, const int* __restrict__ batch) {
    int i = blockIdx.x * blockDim.x + threadIdx.x;
    if (i < N_EDGES) atomicAdd(&g_deg[ei[N_EDGES + i]], 1);
    if (i < N_NODES) atomicAdd(&g_gdeg[batch[i]], 1);
}

__global__ void k_scan_block() {
    __shared__ int sh[1024];
    int t = threadIdx.x;
    int i = blockIdx.x * 1024 + t;
    int v = (i < N_NODES) ? g_deg[i] : 0;
    sh[t] = v;
    __syncthreads();
    for (int off = 1; off < 1024; off <<= 1) {
        int a = (t >= off) ? sh[t - off] : 0;
        __syncthreads();
        sh[t] += a;
        __syncthreads();
    }
    if (i < N_NODES) g_rowptr[i] = sh[t] - v;
    if (t == 1023) g_bsums[blockIdx.x] = sh[1023];
}

// fused: block-sum scan + add + cursor init + total; last block also builds g_gptr
__global__ void k_scan_add2(int nb) {
    __shared__ int sb[128];
    int t = threadIdx.x;
    if (t < 128) sb[t] = (t < nb) ? g_bsums[t] : 0;
    __syncthreads();
    for (int off = 1; off < 128; off <<= 1) {
        int a = (t < 128 && t >= off) ? sb[t - off] : 0;
        __syncthreads();
        if (t < 128) sb[t] += a;
        __syncthreads();
    }
    int i = blockIdx.x * blockDim.x + t;
    if (i < N_NODES) {
        int b = i >> 10;
        int vv = g_rowptr[i] + (b ? sb[b - 1] : 0);
        g_rowptr[i] = vv;
        g_cursor[i] = vv;
    }
    if (i == 0) g_rowptr[N_NODES] = sb[nb - 1];

    if (blockIdx.x == gridDim.x - 1) {    // graph-pointer scan (1024 entries, 4/thread)
        __shared__ int gs[256];
        int b4 = t * 4;
        int a0 = g_gdeg[b4], a1 = g_gdeg[b4 + 1], a2 = g_gdeg[b4 + 2], a3 = g_gdeg[b4 + 3];
        int tot = a0 + a1 + a2 + a3;
        gs[t] = tot;
        __syncthreads();
        for (int off = 1; off < 256; off <<= 1) {
            int a = (t >= off) ? gs[t - off] : 0;
            __syncthreads();
            gs[t] += a;
            __syncthreads();
        }
        int excl = gs[t] - tot;
        g_gptr[b4]     = excl;
        g_gptr[b4 + 1] = excl + a0;
        g_gptr[b4 + 2] = excl + a0 + a1;
        g_gptr[b4 + 3] = excl + a0 + a1 + a2;
        if (t == 255) g_gptr[N_GRAPH] = gs[255];
    }
}

__global__ void k_scatter(const int* __restrict__ ei) {
    int i = blockIdx.x * blockDim.x + threadIdx.x;
    if (i >= N_EDGES) return;
    int s = ei[i];
    int d = ei[N_EDGES + i];
    int pos = atomicAdd(&g_cursor[d], 1);
    g_sd[pos] = make_int2(s, d);        // one random 8B store (vs two random 4B)
}

// warp-per-node sort of src keys (dst is row-constant, stays in place)
__global__ void k_rowsortw() {
    __shared__ int buf[WPB][160];
    int wl = threadIdx.x >> 5, lane = threadIdx.x & 31;
    int n = blockIdx.x * WPB + wl;
    if (n >= N_NODES) return;
    int rs = g_rowptr[n], L = g_rowptr[n + 1] - rs;
    if (L <= 1) return;
    if (L <= 32) {
        int v = (lane < L) ? g_sd[rs + lane].x : 0x7fffffff;
#pragma unroll
        for (int k = 2; k <= 32; k <<= 1) {
#pragma unroll
            for (int j = k >> 1; j; j >>= 1) {
                int o = __shfl_xor_sync(~0u, v, j);
                bool up = ((lane & k) == 0);
                bool lo = ((lane & j) == 0);
                v = (up == lo) ? min(v, o) : max(v, o);
            }
        }
        if (lane < L) g_sd[rs + lane].x = v;
    } else if (L <= 64) {
        int i0 = lane, i1 = lane + 32;
        int v0 = (i0 < L) ? g_sd[rs + i0].x : 0x7fffffff;
        int v1 = (i1 < L) ? g_sd[rs + i1].x : 0x7fffffff;
#pragma unroll
        for (int k = 2; k <= 64; k <<= 1) {
#pragma unroll
            for (int j = k >> 1; j; j >>= 1) {
                if (j >= 32) {
                    int lo = min(v0, v1), hi = max(v0, v1);
                    v0 = lo; v1 = hi;
                } else {
                    int o0 = __shfl_xor_sync(~0u, v0, j);
                    int o1 = __shfl_xor_sync(~0u, v1, j);
                    bool up0 = ((i0 & k) == 0), up1 = ((i1 & k) == 0);
                    bool lo0 = ((i0 & j) == 0), lo1 = ((i1 & j) == 0);
                    v0 = (up0 == lo0) ? min(v0, o0) : max(v0, o0);
                    v1 = (up1 == lo1) ? min(v1, o1) : max(v1, o1);
                }
            }
        }
        if (i0 < L) g_sd[rs + i0].x = v0;
        if (i1 < L) g_sd[rs + i1].x = v1;
    } else if (L <= 160) {
        for (int i = lane; i < L; i += 32) buf[wl][i] = g_sd[rs + i].x;
        __syncwarp();
        for (int p = 0; p < L; p++) {
            for (int i = (p & 1) + 2 * lane; i + 1 < L; i += 64) {
                int a = buf[wl][i], b = buf[wl][i + 1];
                if (a > b) { buf[wl][i] = b; buf[wl][i + 1] = a; }
            }
            __syncwarp();
        }
        for (int i = lane; i < L; i += 32) g_sd[rs + i].x = buf[wl][i];
    } else if (lane == 0) {
        int re = rs + L;
        for (int i = rs + 1; i < re; i++) {
            int key = g_sd[i].x;
            int j = i - 1;
            while (j >= rs && g_sd[j].x > key) { g_sd[j + 1].x = g_sd[j].x; j--; }
            g_sd[j + 1].x = key;
        }
    }
}

// ---------------- layer 1: embed + LN + W1 + logits (8 nodes/warp, f32x2) ----------------
__global__ void k_node1(const int* __restrict__ x, const float* __restrict__ emb,
                        const float* __restrict__ lng, const float* __restrict__ lnb,
                        const float* __restrict__ W1, const float* __restrict__ asr,
                        const float* __restrict__ adt) {
    __shared__ ulonglong2 sW[EMB * 32];
    __shared__ float sxn[WPB][NPW][EMB];
    int tid = threadIdx.x;
    int wl = tid >> 5, lane = tid & 31;
    {
        const ulonglong2* W4 = (const ulonglong2*)W1;
        for (int i = tid; i < EMB * 32; i += NTPB) sW[i] = W4[i];
    }
    int nbase = (blockIdx.x * WPB + wl) * NPW;

#pragma unroll
    for (int j = 0; j < NPW; j++) {
        int n = nbase + j;
        float xn = 0.f;
        if (n < N_NODES) {
            int vi = x[n];
            float xv = emb[vi * EMB + lane];
            float m = xv;
            for (int o = 16; o; o >>= 1) m += __shfl_xor_sync(~0u, m, o);
            m *= (1.f / EMB);
            float dv = xv - m;
            float var = dv * dv;
            for (int o = 16; o; o >>= 1) var += __shfl_xor_sync(~0u, var, o);
            var *= (1.f / EMB);
            xn = dv * rsqrtf(var + 1e-5f) * lng[lane] + lnb[lane];
        }
        sxn[wl][j][lane] = xn;
    }
    __syncthreads();

    unsigned long long accA[NPW], accB[NPW];
#pragma unroll
    for (int j = 0; j < NPW; j++) { accA[j] = 0ull; accB[j] = 0ull; }
#pragma unroll
    for (int k = 0; k < EMB; k += 4) {
        ulonglong2 w0 = sW[(k + 0) * 32 + lane];
        ulonglong2 w1 = sW[(k + 1) * 32 + lane];
        ulonglong2 w2 = sW[(k + 2) * 32 + lane];
        ulonglong2 w3 = sW[(k + 3) * 32 + lane];
#pragma unroll
        for (int j = 0; j < NPW; j++) {
            float4 h4 = *(const float4*)&sxn[wl][j][k];
            unsigned long long p;
            p = pack2(h4.x); fma2(accA[j], w0.x, p); fma2(accB[j], w0.y, p);
            p = pack2(h4.y); fma2(accA[j], w1.x, p); fma2(accB[j], w1.y, p);
            p = pack2(h4.z); fma2(accA[j], w2.x, p); fma2(accB[j], w2.y, p);
            p = pack2(h4.w); fma2(accA[j], w3.x, p); fma2(accB[j], w3.y, p);
        }
    }

    float4 as4 = __ldg((const float4*)asr + lane);
    float4 ad4 = __ldg((const float4*)adt + lane);
#pragma unroll
    for (int j = 0; j < NPW; j++) {
        int n = nbase + j;
        float2 lo = unpack2(accA[j]), hi = unpack2(accB[j]);
        float ps = lo.x * as4.x + lo.y * as4.y + hi.x * as4.z + hi.y * as4.w;
        float pd = lo.x * ad4.x + lo.y * ad4.y + hi.x * ad4.z + hi.y * ad4.w;
        for (int o = 8; o; o >>= 1) {
            ps += __shfl_xor_sync(~0u, ps, o);
            pd += __shfl_xor_sync(~0u, pd, o);
        }
        if (n < N_NODES) {
            store_h4(g_xwh + (size_t)n * DC, lane, lo.x, lo.y, hi.x, hi.y);
            if ((lane & 15) == 0) {
                int h = lane >> 4;
                g_als[n * 2 + h] = ps;
                g_ald[n * 2 + h] = pd;
            }
        }
    }
}

// ---------------- edge-parallel logit precompute (high-MLP random gather context) ----------------
__global__ void k_elog() {
    int p = blockIdx.x * blockDim.x + threadIdx.x;
    if (p >= N_EDGES) return;
    int2 sd = g_sd[p];                                   // one coalesced 8B load
    float2 a = __ldg((const float2*)g_als + sd.x);
    float2 b = __ldg((const float2*)g_ald + sd.y);
    ((float2*)g_elog)[p] = make_float2(lrelu(a.x + b.x, 0.2f), lrelu(a.y + b.y, 0.2f));
}

// ---------------- GAT aggregation: warp/node, 2 edges/iter, no-max softmax ----------------
__global__ void k_agg(const float* __restrict__ bias, float* __restrict__ out2, int layer) {
    int n = blockIdx.x * WPB + (threadIdx.x >> 5);
    int lane = threadIdx.x & 31;
    if (n >= N_NODES) return;

    int rs = g_rowptr[n], re = g_rowptr[n + 1];
    float2 a = *(const float2*)&g_als[2 * n];
    float2 b = *(const float2*)&g_ald[2 * n];
    float es0 = lrelu(a.x + b.x, 0.2f);
    float es1 = lrelu(a.y + b.y, 0.2f);

    // pass 1: plain sum of exp per head (bounded logits; exact-math equal to max-shifted)
    float s0 = 0.f, s1 = 0.f;
    for (int k = rs + lane; k < re; k += 32) {
        float2 e2 = __ldg((const float2*)g_elog + k);
        s0 += __expf(e2.x);
        s1 += __expf(e2.y);
    }
#pragma unroll
    for (int o = 16; o; o >>= 1) {
        s0 += __shfl_xor_sync(~0u, s0, o);
        s1 += __shfl_xor_sync(~0u, s1, o);
    }
    float ps0 = __expf(es0), ps1 = __expf(es1);
    float inv0 = 1.f / (s0 + ps0);
    float inv1 = 1.f / (s1 + ps1);

    int half  = lane >> 4;   // edge slot within iteration
    int s16   = lane & 15;   // feature chunk: 8 halfs [8*s16, 8*s16+8)
    int headb = s16 >> 3;    // head owning my dims

    // pass 2: weighted gather, 2 edges per warp iteration, uint4 (8 halfs) per lane
    float acc[8];
    {
        float pself = (half == 0) ? (headb ? ps1 : ps0) : 0.f;
        uint4 xs = __ldg((const uint4*)(g_xwh + (size_t)n * DC) + s16);
#pragma unroll
        for (int i = 0; i < 8; i++) acc[i] = 0.f;
        h8_fma(acc, xs, pself);
    }
#pragma unroll 4
    for (int k = rs; k < re; k += 2) {
        int kk = k + half;
        int kc = kk < re ? kk : re - 1;
        int src = __ldg(&g_sd[kc].x);                    // broadcast within half-warp
        float2 e2 = __ldg((const float2*)g_elog + kc);
        float e = headb ? e2.y : e2.x;
        float p = (kk < re) ? __expf(e) : 0.f;
        uint4 xv = __ldg((const uint4*)(g_xwh + (size_t)src * DC) + s16);
        h8_fma(acc, xv, p);
    }
#pragma unroll
    for (int i = 0; i < 8; i++) acc[i] += __shfl_xor_sync(~0u, acc[i], 16);

    float invh = headb ? inv1 : inv0;
    int idx = s16 * 2 + half;
    float4 bi = __ldg((const float4*)bias + idx);
    const float* ap = acc + half * 4;
    float4 o;
    o.x = ap[0] * invh + bi.x;
    o.y = ap[1] * invh + bi.y;
    o.z = ap[2] * invh + bi.z;
    o.w = ap[3] * invh + bi.w;
    if (layer == 1) {
        o.x = lrelu(o.x, 0.05f); o.y = lrelu(o.y, 0.05f);
        o.z = lrelu(o.z, 0.05f); o.w = lrelu(o.w, 0.05f);
        ((float4*)g_h1)[(size_t)n * 32 + idx] = o;
    } else {
        ((float4*)out2)[(size_t)n * 32 + idx] = o;
    }
}

// ---------------- layer 2 node transform: h1 @ W2 + logits (8 nodes/warp, smem W2) ----------------
__global__ void k_node2(const float* __restrict__ W2, const float* __restrict__ asr,
                        const float* __restrict__ adt) {
    extern __shared__ float dsm[];
    ulonglong2* sW = (ulonglong2*)dsm;                 // 64KB
    float* sh = dsm + DC * DC;                         // 16KB
    int tid = threadIdx.x;
    int wl = tid >> 5, lane = tid & 31;
    {
        const ulonglong2* W4 = (const ulonglong2*)W2;
        for (int i = tid; i < DC * 32; i += NTPB) sW[i] = W4[i];
    }
    int nbase = (blockIdx.x * WPB + wl) * NPW;
    float* shw = sh + (size_t)wl * NPW * DC;
#pragma unroll
    for (int j = 0; j < NPW; j++) {
        int n = nbase + j;
        float4 v = (n < N_NODES) ? ((const float4*)g_h1)[(size_t)n * 32 + lane]
                                 : make_float4(0.f, 0.f, 0.f, 0.f);
        *(float4*)&shw[j * DC + lane * 4] = v;
    }
    __syncthreads();

    unsigned long long accA[NPW], accB[NPW];
#pragma unroll
    for (int j = 0; j < NPW; j++) { accA[j] = 0ull; accB[j] = 0ull; }
    for (int k = 0; k < DC; k += 4) {
        ulonglong2 w0 = sW[(k + 0) * 32 + lane];
        ulonglong2 w1 = sW[(k + 1) * 32 + lane];
        ulonglong2 w2 = sW[(k + 2) * 32 + lane];
        ulonglong2 w3 = sW[(k + 3) * 32 + lane];
#pragma unroll
        for (int j = 0; j < NPW; j++) {
            float4 h4 = *(const float4*)&shw[j * DC + k];
            unsigned long long p;
            p = pack2(h4.x); fma2(accA[j], w0.x, p); fma2(accB[j], w0.y, p);
            p = pack2(h4.y); fma2(accA[j], w1.x, p); fma2(accB[j], w1.y, p);
            p = pack2(h4.z); fma2(accA[j], w2.x, p); fma2(accB[j], w2.y, p);
            p = pack2(h4.w); fma2(accA[j], w3.x, p); fma2(accB[j], w3.y, p);
        }
    }

    float4 as4 = __ldg((const float4*)asr + lane);
    float4 ad4 = __ldg((const float4*)adt + lane);
#pragma unroll
    for (int j = 0; j < NPW; j++) {
        int n = nbase + j;
        float2 lo = unpack2(accA[j]), hi = unpack2(accB[j]);
        float ps = lo.x * as4.x + lo.y * as4.y + hi.x * as4.z + hi.y * as4.w;
        float pd = lo.x * ad4.x + lo.y * ad4.y + hi.x * ad4.z + hi.y * ad4.w;
        for (int o = 8; o; o >>= 1) {
            ps += __shfl_xor_sync(~0u, ps, o);
            pd += __shfl_xor_sync(~0u, pd, o);
        }
        if (n < N_NODES) {
            store_h4(g_xwh + (size_t)n * DC, lane, lo.x, lo.y, hi.x, hi.y);
            if ((lane & 15) == 0) {
                int h = lane >> 4;
                g_als[n * 2 + h] = ps;
                g_ald[n * 2 + h] = pd;
            }
        }
    }
}

// ---------------- gate MLP (8 nodes/warp, smem gw1) ----------------
__global__ void k_gate(const float* __restrict__ hout, const float* __restrict__ gw1,
                       const float* __restrict__ gb1, const float* __restrict__ gw2,
                       const float* __restrict__ gb2) {
    extern __shared__ float dsm[];
    unsigned long long* sg = (unsigned long long*)dsm;   // 32KB
    float* sh = dsm + DC * 64;                           // 16KB
    int tid = threadIdx.x;
    int wl = tid >> 5, lane = tid & 31;
    {
        const unsigned long long* G = (const unsigned long long*)gw1;
        for (int i = tid; i < DC * 32; i += NTPB) sg[i] = G[i];
    }
    int nbase = (blockIdx.x * WPB + wl) * NPW;
    float* shw = sh + (size_t)wl * NPW * DC;
#pragma unroll
    for (int j = 0; j < NPW; j++) {
        int n = nbase + j;
        float4 v = (n < N_NODES) ? ((const float4*)hout)[(size_t)n * 32 + lane]
                                 : make_float4(0.f, 0.f, 0.f, 0.f);
        *(float4*)&shw[j * DC + lane * 4] = v;
    }
    __syncthreads();

    unsigned long long acc[NPW];
#pragma unroll
    for (int j = 0; j < NPW; j++) acc[j] = 0ull;
    for (int k = 0; k < DC; k += 4) {
        unsigned long long w0 = sg[(k + 0) * 32 + lane];
        unsigned long long w1 = sg[(k + 1) * 32 + lane];
        unsigned long long w2 = sg[(k + 2) * 32 + lane];
        unsigned long long w3 = sg[(k + 3) * 32 + lane];
#pragma unroll
        for (int j = 0; j < NPW; j++) {
            float4 h4 = *(const float4*)&shw[j * DC + k];
            fma2(acc[j], w0, pack2(h4.x));
            fma2(acc[j], w1, pack2(h4.y));
            fma2(acc[j], w2, pack2(h4.z));
            fma2(acc[j], w3, pack2(h4.w));
        }
    }

    float2 gb = __ldg((const float2*)gb1 + lane);
    float2 g2 = __ldg((const float2*)gw2 + lane);
    float gbias = __ldg(gb2);
#pragma unroll
    for (int j = 0; j < NPW; j++) {
        float2 u = unpack2(acc[j]);
        u.x = lrelu(u.x + gb.x, 0.05f);
        u.y = lrelu(u.y + gb.y, 0.05f);
        float ps = u.x * g2.x + u.y * g2.y;
        for (int o = 16; o; o >>= 1) ps += __shfl_xor_sync(~0u, ps, o);
        int n = nbase + j;
        if (lane == 0 && n < N_NODES) g_gate[n] = ps + gbias;
    }
}

// ---------------- per-graph softmax pooling + scratch re-zero for next call ----------------
__global__ void k_pool(const float* __restrict__ hout, float* __restrict__ zout) {
    int g = blockIdx.x;
    int t = threadIdx.x;
    int s = g_gptr[g], e = g_gptr[g + 1];
    __shared__ float red[128];
    __shared__ float wbuf[128];

    float lm = -3.4e38f;
    for (int i = s + t; i < e; i += 128) lm = fmaxf(lm, g_gate[i]);
    red[t] = lm;
    __syncthreads();
    for (int o = 64; o; o >>= 1) { if (t < o) red[t] = fmaxf(red[t], red[t + o]); __syncthreads(); }
    float gm = red[0];
    __syncthreads();

    float ls = 0.f;
    for (int i = s + t; i < e; i += 128) ls += __expf(g_gate[i] - gm);
    red[t] = ls;
    __syncthreads();
    for (int o = 64; o; o >>= 1) { if (t < o) red[t] += red[t + o]; __syncthreads(); }
    float inv = (e > s) ? 1.f / red[0] : 0.f;
    __syncthreads();

    float acc = 0.f;
    for (int base = s; base < e; base += 128) {
        int i = base + t;
        wbuf[t] = (i < e) ? __expf(g_gate[i] - gm) * inv : 0.f;
        __syncthreads();
        int cnt = min(128, e - base);
#pragma unroll 4
        for (int j = 0; j < cnt; j++)
            acc += wbuf[j] * hout[(size_t)(base + j) * DC + t];
        __syncthreads();
    }
    zout[g * DC + t] = acc;

    // re-zero histogram scratch for the next kernel_launch call (1024*128 >= N_NODES)
    int gid = g * 128 + t;
    if (gid < N_NODES) g_deg[gid] = 0;
    if (gid < N_GRAPH) g_gdeg[gid] = 0;
}

// ---------------- launch ----------------
extern "C" void kernel_launch(void* const* d_in, const int* in_sizes, int n_in,
                              void* d_out, int out_size) {
    const int*   x     = (const int*)d_in[0];
    const int*   ei    = (const int*)d_in[1];
    const int*   batch = (const int*)d_in[2];
    const float* emb   = (const float*)d_in[3];
    const float* lng   = (const float*)d_in[4];
    const float* lnb   = (const float*)d_in[5];
    const float* W1    = (const float*)d_in[6];
    const float* as1   = (const float*)d_in[7];
    const float* ad1   = (const float*)d_in[8];
    const float* b1    = (const float*)d_in[9];
    const float* W2    = (const float*)d_in[10];
    const float* as2   = (const float*)d_in[11];
    const float* ad2   = (const float*)d_in[12];
    const float* b2    = (const float*)d_in[13];
    const float* gw1   = (const float*)d_in[14];
    const float* gb1   = (const float*)d_in[15];
    const float* gw2   = (const float*)d_in[16];
    const float* gb2   = (const float*)d_in[17];
    float* out  = (float*)d_out;
    float* zout = out + (size_t)N_NODES * DC;

    const int node2_smem = DC * DC * 4 + WPB * NPW * DC * 4;   // 80 KB
    const int gate_smem  = DC * 64 * 4 + WPB * NPW * DC * 4;   // 48 KB
    cudaFuncSetAttribute(k_node2, cudaFuncAttributeMaxDynamicSharedMemorySize, node2_smem);
    cudaFuncSetAttribute(k_gate,  cudaFuncAttributeMaxDynamicSharedMemorySize, gate_smem);

    int nb_scan = (N_NODES + 1023) / 1024;

    // CSR build + graph segment pointers (5 launches; g_deg/g_gdeg pre-zeroed by prior k_pool)
    k_hist<<<(N_EDGES + 255) / 256, 256>>>(ei, batch);
    k_scan_block<<<nb_scan, 1024>>>();
    k_scan_add2<<<(N_NODES + 255) / 256, 256>>>(nb_scan);
    k_scatter<<<(N_EDGES + 255) / 256, 256>>>(ei);
    k_rowsortw<<<(N_NODES + WPB - 1) / WPB, NTPB>>>();

    int nb_agg  = (N_NODES + WPB - 1) / WPB;
    int nb_blk  = (N_NODES + WPB * NPW - 1) / (WPB * NPW);
    int nb_edge = (N_EDGES + 255) / 256;

    k_node1<<<nb_blk, NTPB>>>(x, emb, lng, lnb, W1, as1, ad1);
    k_elog<<<nb_edge, 256>>>();
    k_agg<<<nb_agg, NTPB>>>(b1, nullptr, 1);
    k_node2<<<nb_blk, NTPB, node2_smem>>>(W2, as2, ad2);
    k_elog<<<nb_edge, 256>>>();
    k_agg<<<nb_agg, NTPB>>>(b2, out, 2);
    k_gate<<<nb_blk, NTPB, gate_smem>>>(out, gw1, gb1, gw2, gb2);
    k_pool<<<N_GRAPH, 128>>>(out, zout);
}

// round 11
// speedup vs baseline: 1.4515x; 1.0804x over previous
#include <cuda_runtime.h>
#include <cuda_fp16.h>

#define N_NODES 100000
#define N_EDGES 1600000
#define N_GRAPH 1024
#define EMB 32
#define DC 128
#define WPB 8       // warps per block
#define NPW 8       // nodes per warp (register blocking in dense kernels)
#define NTPB 256

// ---------------- scratch (static device globals; no allocation) ----------------
__device__ int    g_deg[N_NODES];        // zeroed by k_pool of previous run (init: BSS zero)
__device__ int    g_rowptr[N_NODES + 1];
__device__ int    g_cursor[N_NODES];
__device__ int2   g_sd[N_EDGES];         // {src, dst} per CSR slot
__device__ int    g_bsums[256];
__device__ int    g_gdeg[N_GRAPH];       // zeroed by k_pool of previous run
__device__ int    g_gptr[N_GRAPH + 1];
__device__ __half g_xwh[(size_t)N_NODES * DC];   // fp16 message payload
__device__ float  g_h1[(size_t)N_NODES * DC];
__device__ float  g_als[N_NODES * 2];
__device__ float  g_ald[N_NODES * 2];
__device__ float  g_elog[(size_t)N_EDGES * 2];   // now holds EXP of logits
__device__ float  g_gate[N_NODES];

__device__ __forceinline__ float lrelu(float x, float s) { return x > 0.f ? x : s * x; }

// f32x2 packed helpers (sm_103a; ptxas never emits FFMA2 from C++)
__device__ __forceinline__ unsigned long long pack2(float v) {
    unsigned long long r; asm("mov.b64 %0,{%1,%1};" : "=l"(r) : "f"(v)); return r;
}
__device__ __forceinline__ void fma2(unsigned long long& a, unsigned long long x, unsigned long long p) {
    asm("fma.rn.f32x2 %0,%1,%2,%0;" : "+l"(a) : "l"(x), "l"(p));
}
__device__ __forceinline__ float2 unpack2(unsigned long long v) {
    float2 r; asm("mov.b64 {%0,%1},%2;" : "=f"(r.x), "=f"(r.y) : "l"(v)); return r;
}

// store 4 fp32 as 4 fp16 in one 8B write
__device__ __forceinline__ void store_h4(__half* row, int lane, float a, float b, float c, float d) {
    union { uint2 u; __half2 h[2]; } cv;
    cv.h[0] = __float22half2_rn(make_float2(a, b));
    cv.h[1] = __float22half2_rn(make_float2(c, d));
    ((uint2*)row)[lane] = cv.u;
}

// 8 halfs (uint4) * p accumulated into 8 fp32
__device__ __forceinline__ void h8_fma(float* acc, uint4 v, float p) {
    union { unsigned u; __half2 h; } c;
    float2 f;
    c.u = v.x; f = __half22float2(c.h); acc[0] += f.x * p; acc[1] += f.y * p;
    c.u = v.y; f = __half22float2(c.h); acc[2] += f.x * p; acc[3] += f.y * p;
    c.u = v.z; f = __half22float2(c.h); acc[4] += f.x * p; acc[5] += f.y * p;
    c.u = v.w; f = __half22float2(c.h); acc[6] += f.x * p; acc[7] += f.y * p;
}

// ---------------- CSR build ----------------
__global__ void k_hist(const int* __restrict__ ei, const int* __restrict__ batch) {
    int i = blockIdx.x * blockDim.x + threadIdx.x;
    if (i < N_EDGES) atomicAdd(&g_deg[ei[N_EDGES + i]], 1);
    if (i < N_NODES) atomicAdd(&g_gdeg[batch[i]], 1);
}

__global__ void k_scan_block() {
    __shared__ int sh[1024];
    int t = threadIdx.x;
    int i = blockIdx.x * 1024 + t;
    int v = (i < N_NODES) ? g_deg[i] : 0;
    sh[t] = v;
    __syncthreads();
    for (int off = 1; off < 1024; off <<= 1) {
        int a = (t >= off) ? sh[t - off] : 0;
        __syncthreads();
        sh[t] += a;
        __syncthreads();
    }
    if (i < N_NODES) g_rowptr[i] = sh[t] - v;
    if (t == 1023) g_bsums[blockIdx.x] = sh[1023];
}

// fused: block-sum scan + add + cursor init + total; last block also builds g_gptr
__global__ void k_scan_add2(int nb) {
    __shared__ int sb[128];
    int t = threadIdx.x;
    if (t < 128) sb[t] = (t < nb) ? g_bsums[t] : 0;
    __syncthreads();
    for (int off = 1; off < 128; off <<= 1) {
        int a = (t < 128 && t >= off) ? sb[t - off] : 0;
        __syncthreads();
        if (t < 128) sb[t] += a;
        __syncthreads();
    }
    int i = blockIdx.x * blockDim.x + t;
    if (i < N_NODES) {
        int b = i >> 10;
        int vv = g_rowptr[i] + (b ? sb[b - 1] : 0);
        g_rowptr[i] = vv;
        g_cursor[i] = vv;
    }
    if (i == 0) g_rowptr[N_NODES] = sb[nb - 1];

    if (blockIdx.x == gridDim.x - 1) {    // graph-pointer scan (1024 entries, 4/thread)
        __shared__ int gs[256];
        int b4 = t * 4;
        int a0 = g_gdeg[b4], a1 = g_gdeg[b4 + 1], a2 = g_gdeg[b4 + 2], a3 = g_gdeg[b4 + 3];
        int tot = a0 + a1 + a2 + a3;
        gs[t] = tot;
        __syncthreads();
        for (int off = 1; off < 256; off <<= 1) {
            int a = (t >= off) ? gs[t - off] : 0;
            __syncthreads();
            gs[t] += a;
            __syncthreads();
        }
        int excl = gs[t] - tot;
        g_gptr[b4]     = excl;
        g_gptr[b4 + 1] = excl + a0;
        g_gptr[b4 + 2] = excl + a0 + a1;
        g_gptr[b4 + 3] = excl + a0 + a1 + a2;
        if (t == 255) g_gptr[N_GRAPH] = gs[255];
    }
}

__global__ void k_scatter(const int* __restrict__ ei) {
    int i = blockIdx.x * blockDim.x + threadIdx.x;
    if (i >= N_EDGES) return;
    int s = ei[i];
    int d = ei[N_EDGES + i];
    int pos = atomicAdd(&g_cursor[d], 1);
    g_sd[pos] = make_int2(s, d);
}

// warp-per-node sort of src keys (dst is row-constant, stays in place)
__global__ void k_rowsortw() {
    __shared__ int buf[WPB][160];
    int wl = threadIdx.x >> 5, lane = threadIdx.x & 31;
    int n = blockIdx.x * WPB + wl;
    if (n >= N_NODES) return;
    int rs = g_rowptr[n], L = g_rowptr[n + 1] - rs;
    if (L <= 1) return;
    if (L <= 32) {
        int v = (lane < L) ? g_sd[rs + lane].x : 0x7fffffff;
#pragma unroll
        for (int k = 2; k <= 32; k <<= 1) {
#pragma unroll
            for (int j = k >> 1; j; j >>= 1) {
                int o = __shfl_xor_sync(~0u, v, j);
                bool up = ((lane & k) == 0);
                bool lo = ((lane & j) == 0);
                v = (up == lo) ? min(v, o) : max(v, o);
            }
        }
        if (lane < L) g_sd[rs + lane].x = v;
    } else if (L <= 64) {
        int i0 = lane, i1 = lane + 32;
        int v0 = (i0 < L) ? g_sd[rs + i0].x : 0x7fffffff;
        int v1 = (i1 < L) ? g_sd[rs + i1].x : 0x7fffffff;
#pragma unroll
        for (int k = 2; k <= 64; k <<= 1) {
#pragma unroll
            for (int j = k >> 1; j; j >>= 1) {
                if (j >= 32) {
                    int lo = min(v0, v1), hi = max(v0, v1);
                    v0 = lo; v1 = hi;
                } else {
                    int o0 = __shfl_xor_sync(~0u, v0, j);
                    int o1 = __shfl_xor_sync(~0u, v1, j);
                    bool up0 = ((i0 & k) == 0), up1 = ((i1 & k) == 0);
                    bool lo0 = ((i0 & j) == 0), lo1 = ((i1 & j) == 0);
                    v0 = (up0 == lo0) ? min(v0, o0) : max(v0, o0);
                    v1 = (up1 == lo1) ? min(v1, o1) : max(v1, o1);
                }
            }
        }
        if (i0 < L) g_sd[rs + i0].x = v0;
        if (i1 < L) g_sd[rs + i1].x = v1;
    } else if (L <= 160) {
        for (int i = lane; i < L; i += 32) buf[wl][i] = g_sd[rs + i].x;
        __syncwarp();
        for (int p = 0; p < L; p++) {
            for (int i = (p & 1) + 2 * lane; i + 1 < L; i += 64) {
                int a = buf[wl][i], b = buf[wl][i + 1];
                if (a > b) { buf[wl][i] = b; buf[wl][i + 1] = a; }
            }
            __syncwarp();
        }
        for (int i = lane; i < L; i += 32) g_sd[rs + i].x = buf[wl][i];
    } else if (lane == 0) {
        int re = rs + L;
        for (int i = rs + 1; i < re; i++) {
            int key = g_sd[i].x;
            int j = i - 1;
            while (j >= rs && g_sd[j].x > key) { g_sd[j + 1].x = g_sd[j].x; j--; }
            g_sd[j + 1].x = key;
        }
    }
}

// ---------------- layer 1: embed + LN + W1 + logits (8 nodes/warp, f32x2) ----------------
__global__ void k_node1(const int* __restrict__ x, const float* __restrict__ emb,
                        const float* __restrict__ lng, const float* __restrict__ lnb,
                        const float* __restrict__ W1, const float* __restrict__ asr,
                        const float* __restrict__ adt) {
    __shared__ ulonglong2 sW[EMB * 32];
    __shared__ float sxn[WPB][NPW][EMB];
    int tid = threadIdx.x;
    int wl = tid >> 5, lane = tid & 31;
    {
        const ulonglong2* W4 = (const ulonglong2*)W1;
        for (int i = tid; i < EMB * 32; i += NTPB) sW[i] = W4[i];
    }
    int nbase = (blockIdx.x * WPB + wl) * NPW;

#pragma unroll
    for (int j = 0; j < NPW; j++) {
        int n = nbase + j;
        float xn = 0.f;
        if (n < N_NODES) {
            int vi = x[n];
            float xv = emb[vi * EMB + lane];
            float m = xv;
            for (int o = 16; o; o >>= 1) m += __shfl_xor_sync(~0u, m, o);
            m *= (1.f / EMB);
            float dv = xv - m;
            float var = dv * dv;
            for (int o = 16; o; o >>= 1) var += __shfl_xor_sync(~0u, var, o);
            var *= (1.f / EMB);
            xn = dv * rsqrtf(var + 1e-5f) * lng[lane] + lnb[lane];
        }
        sxn[wl][j][lane] = xn;
    }
    __syncthreads();

    unsigned long long accA[NPW], accB[NPW];
#pragma unroll
    for (int j = 0; j < NPW; j++) { accA[j] = 0ull; accB[j] = 0ull; }
#pragma unroll
    for (int k = 0; k < EMB; k += 4) {
        ulonglong2 w0 = sW[(k + 0) * 32 + lane];
        ulonglong2 w1 = sW[(k + 1) * 32 + lane];
        ulonglong2 w2 = sW[(k + 2) * 32 + lane];
        ulonglong2 w3 = sW[(k + 3) * 32 + lane];
#pragma unroll
        for (int j = 0; j < NPW; j++) {
            float4 h4 = *(const float4*)&sxn[wl][j][k];
            unsigned long long p;
            p = pack2(h4.x); fma2(accA[j], w0.x, p); fma2(accB[j], w0.y, p);
            p = pack2(h4.y); fma2(accA[j], w1.x, p); fma2(accB[j], w1.y, p);
            p = pack2(h4.z); fma2(accA[j], w2.x, p); fma2(accB[j], w2.y, p);
            p = pack2(h4.w); fma2(accA[j], w3.x, p); fma2(accB[j], w3.y, p);
        }
    }

    float4 as4 = __ldg((const float4*)asr + lane);
    float4 ad4 = __ldg((const float4*)adt + lane);
#pragma unroll
    for (int j = 0; j < NPW; j++) {
        int n = nbase + j;
        float2 lo = unpack2(accA[j]), hi = unpack2(accB[j]);
        float ps = lo.x * as4.x + lo.y * as4.y + hi.x * as4.z + hi.y * as4.w;
        float pd = lo.x * ad4.x + lo.y * ad4.y + hi.x * ad4.z + hi.y * ad4.w;
        for (int o = 8; o; o >>= 1) {
            ps += __shfl_xor_sync(~0u, ps, o);
            pd += __shfl_xor_sync(~0u, pd, o);
        }
        if (n < N_NODES) {
            store_h4(g_xwh + (size_t)n * DC, lane, lo.x, lo.y, hi.x, hi.y);
            if ((lane & 15) == 0) {
                int h = lane >> 4;
                g_als[n * 2 + h] = ps;
                g_ald[n * 2 + h] = pd;
            }
        }
    }
}

// ---------------- edge-parallel: exp(lrelu(logit)) precompute ----------------
__global__ void k_elog() {
    int p = blockIdx.x * blockDim.x + threadIdx.x;
    if (p >= N_EDGES) return;
    int2 sd = g_sd[p];
    float2 a = __ldg((const float2*)g_als + sd.x);
    float2 b = __ldg((const float2*)g_ald + sd.y);
    ((float2*)g_elog)[p] = make_float2(__expf(lrelu(a.x + b.x, 0.2f)),
                                       __expf(lrelu(a.y + b.y, 0.2f)));
}

// ---------------- GAT aggregation: warp/node, register-staged row (no load chains) ----------------
__global__ void k_agg(const float* __restrict__ bias, float* __restrict__ out2, int layer) {
    int n = blockIdx.x * WPB + (threadIdx.x >> 5);
    int lane = threadIdx.x & 31;
    if (n >= N_NODES) return;

    int rs = g_rowptr[n], re = g_rowptr[n + 1];
    int L = re - rs;
    float2 a = *(const float2*)&g_als[2 * n];
    float2 b = *(const float2*)&g_ald[2 * n];
    float ps0 = __expf(lrelu(a.x + b.x, 0.2f));
    float ps1 = __expf(lrelu(a.y + b.y, 0.2f));

    int half  = lane >> 4;   // edge slot within iteration
    int s16   = lane & 15;   // feature chunk: 8 halfs [8*s16, 8*s16+8)
    int headb = s16 >> 3;    // head owning my dims

    float acc[8];
    {
        float pself = (half == 0) ? (headb ? ps1 : ps0) : 0.f;
        uint4 xs = __ldg((const uint4*)(g_xwh + (size_t)n * DC) + s16);
#pragma unroll
        for (int i = 0; i < 8; i++) acc[i] = 0.f;
        h8_fma(acc, xs, pself);
    }

    float s0, s1;
    if (L <= 32) {
        // stage entire row in registers: lane k owns edge rs+k
        int   src_l = (lane < L) ? __ldg(&g_sd[rs + lane].x) : 0;
        float2 e_l  = (lane < L) ? __ldg((const float2*)g_elog + rs + lane)
                                 : make_float2(0.f, 0.f);
        s0 = e_l.x; s1 = e_l.y;
#pragma unroll
        for (int o = 16; o; o >>= 1) {
            s0 += __shfl_xor_sync(~0u, s0, o);
            s1 += __shfl_xor_sync(~0u, s1, o);
        }
        // gather loop: src/p via shuffle (fixed-lat), gathers fully independent
#pragma unroll 4
        for (int j = 0; j < L; j += 2) {
            int jj = (j + half) & 31;
            int srcj = __shfl_sync(~0u, src_l, jj);
            float px = __shfl_sync(~0u, e_l.x, jj);
            float py = __shfl_sync(~0u, e_l.y, jj);
            float p = (j + half < L) ? (headb ? py : px) : 0.f;
            uint4 xv = __ldg((const uint4*)(g_xwh + (size_t)srcj * DC) + s16);
            h8_fma(acc, xv, p);
        }
    } else {
        s0 = 0.f; s1 = 0.f;
        for (int k = rs + lane; k < re; k += 32) {
            float2 e2 = __ldg((const float2*)g_elog + k);
            s0 += e2.x;
            s1 += e2.y;
        }
#pragma unroll
        for (int o = 16; o; o >>= 1) {
            s0 += __shfl_xor_sync(~0u, s0, o);
            s1 += __shfl_xor_sync(~0u, s1, o);
        }
#pragma unroll 4
        for (int k = rs; k < re; k += 2) {
            int kk = k + half;
            int kc = kk < re ? kk : re - 1;
            int src = __ldg(&g_sd[kc].x);
            float2 e2 = __ldg((const float2*)g_elog + kc);
            float p = (kk < re) ? (headb ? e2.y : e2.x) : 0.f;
            uint4 xv = __ldg((const uint4*)(g_xwh + (size_t)src * DC) + s16);
            h8_fma(acc, xv, p);
        }
    }

#pragma unroll
    for (int i = 0; i < 8; i++) acc[i] += __shfl_xor_sync(~0u, acc[i], 16);

    float inv0 = 1.f / (s0 + ps0);
    float inv1 = 1.f / (s1 + ps1);
    float invh = headb ? inv1 : inv0;
    int idx = s16 * 2 + half;
    float4 bi = __ldg((const float4*)bias + idx);
    const float* ap = acc + half * 4;
    float4 o;
    o.x = ap[0] * invh + bi.x;
    o.y = ap[1] * invh + bi.y;
    o.z = ap[2] * invh + bi.z;
    o.w = ap[3] * invh + bi.w;
    if (layer == 1) {
        o.x = lrelu(o.x, 0.05f); o.y = lrelu(o.y, 0.05f);
        o.z = lrelu(o.z, 0.05f); o.w = lrelu(o.w, 0.05f);
        ((float4*)g_h1)[(size_t)n * 32 + idx] = o;
    } else {
        ((float4*)out2)[(size_t)n * 32 + idx] = o;
    }
}

// ---------------- layer 2 node transform: h1 @ W2 + logits (8 nodes/warp, smem W2) ----------------
__global__ void k_node2(const float* __restrict__ W2, const float* __restrict__ asr,
                        const float* __restrict__ adt) {
    extern __shared__ float dsm[];
    ulonglong2* sW = (ulonglong2*)dsm;                 // 64KB
    float* sh = dsm + DC * DC;                         // 16KB
    int tid = threadIdx.x;
    int wl = tid >> 5, lane = tid & 31;
    {
        const ulonglong2* W4 = (const ulonglong2*)W2;
        for (int i = tid; i < DC * 32; i += NTPB) sW[i] = W4[i];
    }
    int nbase = (blockIdx.x * WPB + wl) * NPW;
    float* shw = sh + (size_t)wl * NPW * DC;
#pragma unroll
    for (int j = 0; j < NPW; j++) {
        int n = nbase + j;
        float4 v = (n < N_NODES) ? ((const float4*)g_h1)[(size_t)n * 32 + lane]
                                 : make_float4(0.f, 0.f, 0.f, 0.f);
        *(float4*)&shw[j * DC + lane * 4] = v;
    }
    __syncthreads();

    unsigned long long accA[NPW], accB[NPW];
#pragma unroll
    for (int j = 0; j < NPW; j++) { accA[j] = 0ull; accB[j] = 0ull; }
    for (int k = 0; k < DC; k += 4) {
        ulonglong2 w0 = sW[(k + 0) * 32 + lane];
        ulonglong2 w1 = sW[(k + 1) * 32 + lane];
        ulonglong2 w2 = sW[(k + 2) * 32 + lane];
        ulonglong2 w3 = sW[(k + 3) * 32 + lane];
#pragma unroll
        for (int j = 0; j < NPW; j++) {
            float4 h4 = *(const float4*)&shw[j * DC + k];
            unsigned long long p;
            p = pack2(h4.x); fma2(accA[j], w0.x, p); fma2(accB[j], w0.y, p);
            p = pack2(h4.y); fma2(accA[j], w1.x, p); fma2(accB[j], w1.y, p);
            p = pack2(h4.z); fma2(accA[j], w2.x, p); fma2(accB[j], w2.y, p);
            p = pack2(h4.w); fma2(accA[j], w3.x, p); fma2(accB[j], w3.y, p);
        }
    }

    float4 as4 = __ldg((const float4*)asr + lane);
    float4 ad4 = __ldg((const float4*)adt + lane);
#pragma unroll
    for (int j = 0; j < NPW; j++) {
        int n = nbase + j;
        float2 lo = unpack2(accA[j]), hi = unpack2(accB[j]);
        float ps = lo.x * as4.x + lo.y * as4.y + hi.x * as4.z + hi.y * as4.w;
        float pd = lo.x * ad4.x + lo.y * ad4.y + hi.x * ad4.z + hi.y * ad4.w;
        for (int o = 8; o; o >>= 1) {
            ps += __shfl_xor_sync(~0u, ps, o);
            pd += __shfl_xor_sync(~0u, pd, o);
        }
        if (n < N_NODES) {
            store_h4(g_xwh + (size_t)n * DC, lane, lo.x, lo.y, hi.x, hi.y);
            if ((lane & 15) == 0) {
                int h = lane >> 4;
                g_als[n * 2 + h] = ps;
                g_ald[n * 2 + h] = pd;
            }
        }
    }
}

// ---------------- gate MLP (8 nodes/warp, smem gw1) ----------------
__global__ void k_gate(const float* __restrict__ hout, const float* __restrict__ gw1,
                       const float* __restrict__ gb1, const float* __restrict__ gw2,
                       const float* __restrict__ gb2) {
    extern __shared__ float dsm[];
    unsigned long long* sg = (unsigned long long*)dsm;   // 32KB
    float* sh = dsm + DC * 64;                           // 16KB
    int tid = threadIdx.x;
    int wl = tid >> 5, lane = tid & 31;
    {
        const unsigned long long* G = (const unsigned long long*)gw1;
        for (int i = tid; i < DC * 32; i += NTPB) sg[i] = G[i];
    }
    int nbase = (blockIdx.x * WPB + wl) * NPW;
    float* shw = sh + (size_t)wl * NPW * DC;
#pragma unroll
    for (int j = 0; j < NPW; j++) {
        int n = nbase + j;
        float4 v = (n < N_NODES) ? ((const float4*)hout)[(size_t)n * 32 + lane]
                                 : make_float4(0.f, 0.f, 0.f, 0.f);
        *(float4*)&shw[j * DC + lane * 4] = v;
    }
    __syncthreads();

    unsigned long long acc[NPW];
#pragma unroll
    for (int j = 0; j < NPW; j++) acc[j] = 0ull;
    for (int k = 0; k < DC; k += 4) {
        unsigned long long w0 = sg[(k + 0) * 32 + lane];
        unsigned long long w1 = sg[(k + 1) * 32 + lane];
        unsigned long long w2 = sg[(k + 2) * 32 + lane];
        unsigned long long w3 = sg[(k + 3) * 32 + lane];
#pragma unroll
        for (int j = 0; j < NPW; j++) {
            float4 h4 = *(const float4*)&shw[j * DC + k];
            fma2(acc[j], w0, pack2(h4.x));
            fma2(acc[j], w1, pack2(h4.y));
            fma2(acc[j], w2, pack2(h4.z));
            fma2(acc[j], w3, pack2(h4.w));
        }
    }

    float2 gb = __ldg((const float2*)gb1 + lane);
    float2 g2 = __ldg((const float2*)gw2 + lane);
    float gbias = __ldg(gb2);
#pragma unroll
    for (int j = 0; j < NPW; j++) {
        float2 u = unpack2(acc[j]);
        u.x = lrelu(u.x + gb.x, 0.05f);
        u.y = lrelu(u.y + gb.y, 0.05f);
        float ps = u.x * g2.x + u.y * g2.y;
        for (int o = 16; o; o >>= 1) ps += __shfl_xor_sync(~0u, ps, o);
        int n = nbase + j;
        if (lane == 0 && n < N_NODES) g_gate[n] = ps + gbias;
    }
}

// ---------------- per-graph softmax pooling + scratch re-zero for next call ----------------
__global__ void k_pool(const float* __restrict__ hout, float* __restrict__ zout) {
    int g = blockIdx.x;
    int t = threadIdx.x;
    int s = g_gptr[g], e = g_gptr[g + 1];
    __shared__ float red[128];
    __shared__ float wbuf[128];

    float lm = -3.4e38f;
    for (int i = s + t; i < e; i += 128) lm = fmaxf(lm, g_gate[i]);
    red[t] = lm;
    __syncthreads();
    for (int o = 64; o; o >>= 1) { if (t < o) red[t] = fmaxf(red[t], red[t + o]); __syncthreads(); }
    float gm = red[0];
    __syncthreads();

    float ls = 0.f;
    for (int i = s + t; i < e; i += 128) ls += __expf(g_gate[i] - gm);
    red[t] = ls;
    __syncthreads();
    for (int o = 64; o; o >>= 1) { if (t < o) red[t] += red[t + o]; __syncthreads(); }
    float inv = (e > s) ? 1.f / red[0] : 0.f;
    __syncthreads();

    float acc = 0.f;
    for (int base = s; base < e; base += 128) {
        int i = base + t;
        wbuf[t] = (i < e) ? __expf(g_gate[i] - gm) * inv : 0.f;
        __syncthreads();
        int cnt = min(128, e - base);
#pragma unroll 4
        for (int j = 0; j < cnt; j++)
            acc += wbuf[j] * hout[(size_t)(base + j) * DC + t];
        __syncthreads();
    }
    zout[g * DC + t] = acc;

    // re-zero histogram scratch for the next kernel_launch call (1024*128 >= N_NODES)
    int gid = g * 128 + t;
    if (gid < N_NODES) g_deg[gid] = 0;
    if (gid < N_GRAPH) g_gdeg[gid] = 0;
}

// ---------------- launch ----------------
extern "C" void kernel_launch(void* const* d_in, const int* in_sizes, int n_in,
                              void* d_out, int out_size) {
    const int*   x     = (const int*)d_in[0];
    const int*   ei    = (const int*)d_in[1];
    const int*   batch = (const int*)d_in[2];
    const float* emb   = (const float*)d_in[3];
    const float* lng   = (const float*)d_in[4];
    const float* lnb   = (const float*)d_in[5];
    const float* W1    = (const float*)d_in[6];
    const float* as1   = (const float*)d_in[7];
    const float* ad1   = (const float*)d_in[8];
    const float* b1    = (const float*)d_in[9];
    const float* W2    = (const float*)d_in[10];
    const float* as2   = (const float*)d_in[11];
    const float* ad2   = (const float*)d_in[12];
    const float* b2    = (const float*)d_in[13];
    const float* gw1   = (const float*)d_in[14];
    const float* gb1   = (const float*)d_in[15];
    const float* gw2   = (const float*)d_in[16];
    const float* gb2   = (const float*)d_in[17];
    float* out  = (float*)d_out;
    float* zout = out + (size_t)N_NODES * DC;

    const int node2_smem = DC * DC * 4 + WPB * NPW * DC * 4;   // 80 KB
    const int gate_smem  = DC * 64 * 4 + WPB * NPW * DC * 4;   // 48 KB
    cudaFuncSetAttribute(k_node2, cudaFuncAttributeMaxDynamicSharedMemorySize, node2_smem);
    cudaFuncSetAttribute(k_gate,  cudaFuncAttributeMaxDynamicSharedMemorySize, gate_smem);

    int nb_scan = (N_NODES + 1023) / 1024;

    // CSR build + graph segment pointers (5 launches; g_deg/g_gdeg pre-zeroed by prior k_pool)
    k_hist<<<(N_EDGES + 255) / 256, 256>>>(ei, batch);
    k_scan_block<<<nb_scan, 1024>>>();
    k_scan_add2<<<(N_NODES + 255) / 256, 256>>>(nb_scan);
    k_scatter<<<(N_EDGES + 255) / 256, 256>>>(ei);
    k_rowsortw<<<(N_NODES + WPB - 1) / WPB, NTPB>>>();

    int nb_agg  = (N_NODES + WPB - 1) / WPB;
    int nb_blk  = (N_NODES + WPB * NPW - 1) / (WPB * NPW);
    int nb_edge = (N_EDGES + 255) / 256;

    k_node1<<<nb_blk, NTPB>>>(x, emb, lng, lnb, W1, as1, ad1);
    k_elog<<<nb_edge, 256>>>();
    k_agg<<<nb_agg, NTPB>>>(b1, nullptr, 1);
    k_node2<<<nb_blk, NTPB, node2_smem>>>(W2, as2, ad2);
    k_elog<<<nb_edge, 256>>>();
    k_agg<<<nb_agg, NTPB>>>(b2, out, 2);
    k_gate<<<nb_blk, NTPB, gate_smem>>>(out, gw1, gb1, gw2, gb2);
    k_pool<<<N_GRAPH, 128>>>(out, zout);
}

// round 12
// speedup vs baseline: 1.6888x; 1.1635x over previous
#include <cuda_runtime.h>
#include <cuda_fp16.h>

#define N_NODES 100000
#define N_EDGES 1600000
#define N_GRAPH 1024
#define EMB 32
#define DC 128
#define WPB 8       // warps per block
#define NPW 8       // nodes per warp (register blocking in dense kernels)
#define NTPB 256

// ---------------- scratch (static device globals; no allocation) ----------------
__device__ int    g_deg[N_NODES];        // zeroed by k_pool of previous run (init: BSS zero)
__device__ int    g_rowptr[N_NODES + 1];
__device__ int    g_cursor[N_NODES];
__device__ int2   g_sd[N_EDGES];         // {src, dst} per CSR slot
__device__ int    g_bsums[256];
__device__ int    g_gdeg[N_GRAPH];       // zeroed by k_pool of previous run
__device__ int    g_gptr[N_GRAPH + 1];
__device__ __half g_xwh[(size_t)N_NODES * DC];   // fp16 message payload
__device__ __half g_h1h[(size_t)N_NODES * DC];   // fp16 layer-1 output (node2 A operand)
__device__ float  g_als[N_NODES * 2];
__device__ float  g_ald[N_NODES * 2];
__device__ float  g_elog[(size_t)N_EDGES * 2];   // EXP of logits
__device__ float  g_gate[N_NODES];

__device__ __forceinline__ float lrelu(float x, float s) { return x > 0.f ? x : s * x; }

// f32x2 packed helpers (sm_103a; ptxas never emits FFMA2 from C++)
__device__ __forceinline__ unsigned long long pack2(float v) {
    unsigned long long r; asm("mov.b64 %0,{%1,%1};" : "=l"(r) : "f"(v)); return r;
}
__device__ __forceinline__ void fma2(unsigned long long& a, unsigned long long x, unsigned long long p) {
    asm("fma.rn.f32x2 %0,%1,%2,%0;" : "+l"(a) : "l"(x), "l"(p));
}
__device__ __forceinline__ float2 unpack2(unsigned long long v) {
    float2 r; asm("mov.b64 {%0,%1},%2;" : "=f"(r.x), "=f"(r.y) : "l"(v)); return r;
}

// store 4 fp32 as 4 fp16 in one 8B write
__device__ __forceinline__ void store_h4(__half* row, int lane, float a, float b, float c, float d) {
    union { uint2 u; __half2 h[2]; } cv;
    cv.h[0] = __float22half2_rn(make_float2(a, b));
    cv.h[1] = __float22half2_rn(make_float2(c, d));
    ((uint2*)row)[lane] = cv.u;
}

// 8 halfs (uint4) * p accumulated into 8 fp32
__device__ __forceinline__ void h8_fma(float* acc, uint4 v, float p) {
    union { unsigned u; __half2 h; } c;
    float2 f;
    c.u = v.x; f = __half22float2(c.h); acc[0] += f.x * p; acc[1] += f.y * p;
    c.u = v.y; f = __half22float2(c.h); acc[2] += f.x * p; acc[3] += f.y * p;
    c.u = v.z; f = __half22float2(c.h); acc[4] += f.x * p; acc[5] += f.y * p;
    c.u = v.w; f = __half22float2(c.h); acc[6] += f.x * p; acc[7] += f.y * p;
}

__device__ __forceinline__ unsigned s2u(const void* p) {
    unsigned a;
    asm("{.reg .u64 t; cvta.to.shared.u64 t,%1; cvt.u32.u64 %0,t;}" : "=r"(a) : "l"(p));
    return a;
}

#define LDSM4(r0, r1, r2, r3, addr) \
    asm volatile("ldmatrix.sync.aligned.m8n8.x4.shared.b16 {%0,%1,%2,%3},[%4];" \
                 : "=r"(r0), "=r"(r1), "=r"(r2), "=r"(r3) : "r"(addr))
#define LDSM4T(r0, r1, r2, r3, addr) \
    asm volatile("ldmatrix.sync.aligned.m8n8.x4.trans.shared.b16 {%0,%1,%2,%3},[%4];" \
                 : "=r"(r0), "=r"(r1), "=r"(r2), "=r"(r3) : "r"(addr))
#define MMA16816(C, a0, a1, a2, a3, b0, b1) \
    asm volatile("mma.sync.aligned.m16n8k16.row.col.f32.f16.f16.f32 " \
                 "{%0,%1,%2,%3},{%4,%5,%6,%7},{%8,%9},{%0,%1,%2,%3};" \
                 : "+f"((C)[0]), "+f"((C)[1]), "+f"((C)[2]), "+f"((C)[3]) \
                 : "r"(a0), "r"(a1), "r"(a2), "r"(a3), "r"(b0), "r"(b1))

// ---------------- CSR build ----------------
__global__ void k_hist(const int* __restrict__ ei, const int* __restrict__ batch) {
    int i = blockIdx.x * blockDim.x + threadIdx.x;
    if (i < N_EDGES) atomicAdd(&g_deg[ei[N_EDGES + i]], 1);
    if (i < N_NODES) atomicAdd(&g_gdeg[batch[i]], 1);
}

__global__ void k_scan_block() {
    __shared__ int sh[1024];
    int t = threadIdx.x;
    int i = blockIdx.x * 1024 + t;
    int v = (i < N_NODES) ? g_deg[i] : 0;
    sh[t] = v;
    __syncthreads();
    for (int off = 1; off < 1024; off <<= 1) {
        int a = (t >= off) ? sh[t - off] : 0;
        __syncthreads();
        sh[t] += a;
        __syncthreads();
    }
    if (i < N_NODES) g_rowptr[i] = sh[t] - v;
    if (t == 1023) g_bsums[blockIdx.x] = sh[1023];
}

// fused: block-sum scan + add + cursor init + total; last block also builds g_gptr
__global__ void k_scan_add2(int nb) {
    __shared__ int sb[128];
    int t = threadIdx.x;
    if (t < 128) sb[t] = (t < nb) ? g_bsums[t] : 0;
    __syncthreads();
    for (int off = 1; off < 128; off <<= 1) {
        int a = (t < 128 && t >= off) ? sb[t - off] : 0;
        __syncthreads();
        if (t < 128) sb[t] += a;
        __syncthreads();
    }
    int i = blockIdx.x * blockDim.x + t;
    if (i < N_NODES) {
        int b = i >> 10;
        int vv = g_rowptr[i] + (b ? sb[b - 1] : 0);
        g_rowptr[i] = vv;
        g_cursor[i] = vv;
    }
    if (i == 0) g_rowptr[N_NODES] = sb[nb - 1];

    if (blockIdx.x == gridDim.x - 1) {    // graph-pointer scan (1024 entries, 4/thread)
        __shared__ int gs[256];
        int b4 = t * 4;
        int a0 = g_gdeg[b4], a1 = g_gdeg[b4 + 1], a2 = g_gdeg[b4 + 2], a3 = g_gdeg[b4 + 3];
        int tot = a0 + a1 + a2 + a3;
        gs[t] = tot;
        __syncthreads();
        for (int off = 1; off < 256; off <<= 1) {
            int a = (t >= off) ? gs[t - off] : 0;
            __syncthreads();
            gs[t] += a;
            __syncthreads();
        }
        int excl = gs[t] - tot;
        g_gptr[b4]     = excl;
        g_gptr[b4 + 1] = excl + a0;
        g_gptr[b4 + 2] = excl + a0 + a1;
        g_gptr[b4 + 3] = excl + a0 + a1 + a2;
        if (t == 255) g_gptr[N_GRAPH] = gs[255];
    }
}

__global__ void k_scatter(const int* __restrict__ ei) {
    int i = blockIdx.x * blockDim.x + threadIdx.x;
    if (i >= N_EDGES) return;
    int s = ei[i];
    int d = ei[N_EDGES + i];
    int pos = atomicAdd(&g_cursor[d], 1);
    g_sd[pos] = make_int2(s, d);
}

// warp-per-node sort of src keys (dst is row-constant, stays in place)
__global__ void k_rowsortw() {
    __shared__ int buf[WPB][160];
    int wl = threadIdx.x >> 5, lane = threadIdx.x & 31;
    int n = blockIdx.x * WPB + wl;
    if (n >= N_NODES) return;
    int rs = g_rowptr[n], L = g_rowptr[n + 1] - rs;
    if (L <= 1) return;
    if (L <= 32) {
        int v = (lane < L) ? g_sd[rs + lane].x : 0x7fffffff;
#pragma unroll
        for (int k = 2; k <= 32; k <<= 1) {
#pragma unroll
            for (int j = k >> 1; j; j >>= 1) {
                int o = __shfl_xor_sync(~0u, v, j);
                bool up = ((lane & k) == 0);
                bool lo = ((lane & j) == 0);
                v = (up == lo) ? min(v, o) : max(v, o);
            }
        }
        if (lane < L) g_sd[rs + lane].x = v;
    } else if (L <= 64) {
        int i0 = lane, i1 = lane + 32;
        int v0 = (i0 < L) ? g_sd[rs + i0].x : 0x7fffffff;
        int v1 = (i1 < L) ? g_sd[rs + i1].x : 0x7fffffff;
#pragma unroll
        for (int k = 2; k <= 64; k <<= 1) {
#pragma unroll
            for (int j = k >> 1; j; j >>= 1) {
                if (j >= 32) {
                    int lo = min(v0, v1), hi = max(v0, v1);
                    v0 = lo; v1 = hi;
                } else {
                    int o0 = __shfl_xor_sync(~0u, v0, j);
                    int o1 = __shfl_xor_sync(~0u, v1, j);
                    bool up0 = ((i0 & k) == 0), up1 = ((i1 & k) == 0);
                    bool lo0 = ((i0 & j) == 0), lo1 = ((i1 & j) == 0);
                    v0 = (up0 == lo0) ? min(v0, o0) : max(v0, o0);
                    v1 = (up1 == lo1) ? min(v1, o1) : max(v1, o1);
                }
            }
        }
        if (i0 < L) g_sd[rs + i0].x = v0;
        if (i1 < L) g_sd[rs + i1].x = v1;
    } else if (L <= 160) {
        for (int i = lane; i < L; i += 32) buf[wl][i] = g_sd[rs + i].x;
        __syncwarp();
        for (int p = 0; p < L; p++) {
            for (int i = (p & 1) + 2 * lane; i + 1 < L; i += 64) {
                int a = buf[wl][i], b = buf[wl][i + 1];
                if (a > b) { buf[wl][i] = b; buf[wl][i + 1] = a; }
            }
            __syncwarp();
        }
        for (int i = lane; i < L; i += 32) g_sd[rs + i].x = buf[wl][i];
    } else if (lane == 0) {
        int re = rs + L;
        for (int i = rs + 1; i < re; i++) {
            int key = g_sd[i].x;
            int j = i - 1;
            while (j >= rs && g_sd[j].x > key) { g_sd[j + 1].x = g_sd[j].x; j--; }
            g_sd[j + 1].x = key;
        }
    }
}

// ---------------- layer 1: embed + LN + W1 + logits (8 nodes/warp, f32x2) ----------------
__global__ void k_node1(const int* __restrict__ x, const float* __restrict__ emb,
                        const float* __restrict__ lng, const float* __restrict__ lnb,
                        const float* __restrict__ W1, const float* __restrict__ asr,
                        const float* __restrict__ adt) {
    __shared__ ulonglong2 sW[EMB * 32];
    __shared__ float sxn[WPB][NPW][EMB];
    int tid = threadIdx.x;
    int wl = tid >> 5, lane = tid & 31;
    {
        const ulonglong2* W4 = (const ulonglong2*)W1;
        for (int i = tid; i < EMB * 32; i += NTPB) sW[i] = W4[i];
    }
    int nbase = (blockIdx.x * WPB + wl) * NPW;

#pragma unroll
    for (int j = 0; j < NPW; j++) {
        int n = nbase + j;
        float xn = 0.f;
        if (n < N_NODES) {
            int vi = x[n];
            float xv = emb[vi * EMB + lane];
            float m = xv;
            for (int o = 16; o; o >>= 1) m += __shfl_xor_sync(~0u, m, o);
            m *= (1.f / EMB);
            float dv = xv - m;
            float var = dv * dv;
            for (int o = 16; o; o >>= 1) var += __shfl_xor_sync(~0u, var, o);
            var *= (1.f / EMB);
            xn = dv * rsqrtf(var + 1e-5f) * lng[lane] + lnb[lane];
        }
        sxn[wl][j][lane] = xn;
    }
    __syncthreads();

    unsigned long long accA[NPW], accB[NPW];
#pragma unroll
    for (int j = 0; j < NPW; j++) { accA[j] = 0ull; accB[j] = 0ull; }
#pragma unroll
    for (int k = 0; k < EMB; k += 4) {
        ulonglong2 w0 = sW[(k + 0) * 32 + lane];
        ulonglong2 w1 = sW[(k + 1) * 32 + lane];
        ulonglong2 w2 = sW[(k + 2) * 32 + lane];
        ulonglong2 w3 = sW[(k + 3) * 32 + lane];
#pragma unroll
        for (int j = 0; j < NPW; j++) {
            float4 h4 = *(const float4*)&sxn[wl][j][k];
            unsigned long long p;
            p = pack2(h4.x); fma2(accA[j], w0.x, p); fma2(accB[j], w0.y, p);
            p = pack2(h4.y); fma2(accA[j], w1.x, p); fma2(accB[j], w1.y, p);
            p = pack2(h4.z); fma2(accA[j], w2.x, p); fma2(accB[j], w2.y, p);
            p = pack2(h4.w); fma2(accA[j], w3.x, p); fma2(accB[j], w3.y, p);
        }
    }

    float4 as4 = __ldg((const float4*)asr + lane);
    float4 ad4 = __ldg((const float4*)adt + lane);
#pragma unroll
    for (int j = 0; j < NPW; j++) {
        int n = nbase + j;
        float2 lo = unpack2(accA[j]), hi = unpack2(accB[j]);
        float ps = lo.x * as4.x + lo.y * as4.y + hi.x * as4.z + hi.y * as4.w;
        float pd = lo.x * ad4.x + lo.y * ad4.y + hi.x * ad4.z + hi.y * ad4.w;
        for (int o = 8; o; o >>= 1) {
            ps += __shfl_xor_sync(~0u, ps, o);
            pd += __shfl_xor_sync(~0u, pd, o);
        }
        if (n < N_NODES) {
            store_h4(g_xwh + (size_t)n * DC, lane, lo.x, lo.y, hi.x, hi.y);
            if ((lane & 15) == 0) {
                int h = lane >> 4;
                g_als[n * 2 + h] = ps;
                g_ald[n * 2 + h] = pd;
            }
        }
    }
}

// ---------------- edge-parallel: exp(lrelu(logit)) precompute ----------------
__global__ void k_elog() {
    int p = blockIdx.x * blockDim.x + threadIdx.x;
    if (p >= N_EDGES) return;
    int2 sd = g_sd[p];
    float2 a = __ldg((const float2*)g_als + sd.x);
    float2 b = __ldg((const float2*)g_ald + sd.y);
    ((float2*)g_elog)[p] = make_float2(__expf(lrelu(a.x + b.x, 0.2f)),
                                       __expf(lrelu(a.y + b.y, 0.2f)));
}

// ---------------- GAT aggregation: warp/node, register-staged row ----------------
__global__ void k_agg(const float* __restrict__ bias, float* __restrict__ out2, int layer) {
    int n = blockIdx.x * WPB + (threadIdx.x >> 5);
    int lane = threadIdx.x & 31;
    if (n >= N_NODES) return;

    int rs = g_rowptr[n], re = g_rowptr[n + 1];
    int L = re - rs;
    float2 a = *(const float2*)&g_als[2 * n];
    float2 b = *(const float2*)&g_ald[2 * n];
    float ps0 = __expf(lrelu(a.x + b.x, 0.2f));
    float ps1 = __expf(lrelu(a.y + b.y, 0.2f));

    int half  = lane >> 4;
    int s16   = lane & 15;
    int headb = s16 >> 3;

    float acc[8];
    {
        float pself = (half == 0) ? (headb ? ps1 : ps0) : 0.f;
        uint4 xs = __ldg((const uint4*)(g_xwh + (size_t)n * DC) + s16);
#pragma unroll
        for (int i = 0; i < 8; i++) acc[i] = 0.f;
        h8_fma(acc, xs, pself);
    }

    float s0, s1;
    if (L <= 32) {
        int   src_l = (lane < L) ? __ldg(&g_sd[rs + lane].x) : 0;
        float2 e_l  = (lane < L) ? __ldg((const float2*)g_elog + rs + lane)
                                 : make_float2(0.f, 0.f);
        s0 = e_l.x; s1 = e_l.y;
#pragma unroll
        for (int o = 16; o; o >>= 1) {
            s0 += __shfl_xor_sync(~0u, s0, o);
            s1 += __shfl_xor_sync(~0u, s1, o);
        }
#pragma unroll 4
        for (int j = 0; j < L; j += 2) {
            int jj = (j + half) & 31;
            int srcj = __shfl_sync(~0u, src_l, jj);
            float px = __shfl_sync(~0u, e_l.x, jj);
            float py = __shfl_sync(~0u, e_l.y, jj);
            float p = (j + half < L) ? (headb ? py : px) : 0.f;
            uint4 xv = __ldg((const uint4*)(g_xwh + (size_t)srcj * DC) + s16);
            h8_fma(acc, xv, p);
        }
    } else {
        s0 = 0.f; s1 = 0.f;
        for (int k = rs + lane; k < re; k += 32) {
            float2 e2 = __ldg((const float2*)g_elog + k);
            s0 += e2.x;
            s1 += e2.y;
        }
#pragma unroll
        for (int o = 16; o; o >>= 1) {
            s0 += __shfl_xor_sync(~0u, s0, o);
            s1 += __shfl_xor_sync(~0u, s1, o);
        }
#pragma unroll 4
        for (int k = rs; k < re; k += 2) {
            int kk = k + half;
            int kc = kk < re ? kk : re - 1;
            int src = __ldg(&g_sd[kc].x);
            float2 e2 = __ldg((const float2*)g_elog + kc);
            float p = (kk < re) ? (headb ? e2.y : e2.x) : 0.f;
            uint4 xv = __ldg((const uint4*)(g_xwh + (size_t)src * DC) + s16);
            h8_fma(acc, xv, p);
        }
    }

#pragma unroll
    for (int i = 0; i < 8; i++) acc[i] += __shfl_xor_sync(~0u, acc[i], 16);

    float inv0 = 1.f / (s0 + ps0);
    float inv1 = 1.f / (s1 + ps1);
    float invh = headb ? inv1 : inv0;
    int idx = s16 * 2 + half;
    float4 bi = __ldg((const float4*)bias + idx);
    const float* ap = acc + half * 4;
    float4 o;
    o.x = ap[0] * invh + bi.x;
    o.y = ap[1] * invh + bi.y;
    o.z = ap[2] * invh + bi.z;
    o.w = ap[3] * invh + bi.w;
    if (layer == 1) {
        o.x = lrelu(o.x, 0.05f); o.y = lrelu(o.y, 0.05f);
        o.z = lrelu(o.z, 0.05f); o.w = lrelu(o.w, 0.05f);
        store_h4(g_h1h + (size_t)n * DC, idx, o.x, o.y, o.z, o.w);   // fp16 for MMA node2
    } else {
        ((float4*)out2)[(size_t)n * 32 + idx] = o;
    }
}

// ---------------- layer 2 node transform via HMMA: h1h @ W2 + logits ----------------
// block: 256 thr / 8 warps; warp computes 16 nodes x 128 dims; smem A+B padded pitch 272B.
#define PITCH_H 136   // halfs per smem row (128 + 8 pad)
__global__ void k_node2m(const float* __restrict__ W2, const float* __restrict__ asr,
                         const float* __restrict__ adt) {
    extern __shared__ char dsm[];
    __half* sA = (__half*)dsm;                                 // 128 x PITCH_H
    __half* sB = (__half*)(dsm + 128 * PITCH_H * 2);           // 128 x PITCH_H
    float*  sAs = (float*)(dsm + 2 * 128 * PITCH_H * 2);       // 128
    float*  sAd = sAs + 128;

    int tid = threadIdx.x;
    int wl = tid >> 5, lane = tid & 31;
    int bb = blockIdx.x * 128;

    if (tid < 128) { sAs[tid] = asr[tid]; sAd[tid] = adt[tid]; }
    // stage B: W2 fp32 -> fp16
    for (int i = tid; i < 128 * 64; i += NTPB) {
        int k = i >> 6, c2 = i & 63;
        float2 w = *(const float2*)(W2 + k * 128 + c2 * 2);
        *(__half2*)(sB + k * PITCH_H + c2 * 2) = __float22half2_rn(w);
    }
    // stage A: g_h1h rows
    for (int i = tid; i < 128 * 16; i += NTPB) {
        int r = i >> 4, c = i & 15;
        int rg = bb + r; if (rg >= N_NODES) rg = N_NODES - 1;
        uint4 v = *(const uint4*)(g_h1h + (size_t)rg * DC + c * 8);
        *(uint4*)(sA + r * PITCH_H + c * 8) = v;
    }
    __syncthreads();

    float C[16][4];
#pragma unroll
    for (int t = 0; t < 16; t++) { C[t][0] = 0.f; C[t][1] = 0.f; C[t][2] = 0.f; C[t][3] = 0.f; }

    int g = lane >> 3;
    int rrow = (lane & 7) + ((g & 1) << 3);          // row-within-16 for ldmatrix
    unsigned aBase = s2u(sA + wl * 16 * PITCH_H) + rrow * (PITCH_H * 2) + ((g >> 1) << 4);
    unsigned bBase = s2u(sB) + rrow * (PITCH_H * 2) + ((g >> 1) << 4);

#pragma unroll
    for (int kg = 0; kg < 8; kg++) {
        unsigned a0, a1, a2, a3;
        LDSM4(a0, a1, a2, a3, aBase + kg * 32);
#pragma unroll
        for (int nt = 0; nt < 8; nt++) {
            unsigned b0, b1, b2, b3;
            LDSM4T(b0, b1, b2, b3, bBase + kg * 16 * (PITCH_H * 2) + nt * 32);
            MMA16816(C[nt * 2],     a0, a1, a2, a3, b0, b1);
            MMA16816(C[nt * 2 + 1], a0, a1, a2, a3, b2, b3);
        }
    }

    // epilogue: store fp16 payload + logits
    int q = lane & 3;
    int r0 = wl * 16 + (lane >> 2);
    int n0 = bb + r0, n1 = n0 + 8;
    float psA0 = 0.f, psB0 = 0.f, pdA0 = 0.f, pdB0 = 0.f;   // row r0: head0/head1, as/ad
    float psA1 = 0.f, psB1 = 0.f, pdA1 = 0.f, pdB1 = 0.f;   // row r0+8
#pragma unroll
    for (int nt = 0; nt < 16; nt++) {
        int col = nt * 8 + q * 2;
        float c0 = C[nt][0], c1 = C[nt][1], c2 = C[nt][2], c3 = C[nt][3];
        if (n0 < N_NODES)
            *(__half2*)(g_xwh + (size_t)n0 * DC + col) = __floats2half2_rn(c0, c1);
        if (n1 < N_NODES)
            *(__half2*)(g_xwh + (size_t)n1 * DC + col) = __floats2half2_rn(c2, c3);
        float as0 = sAs[col], as1 = sAs[col + 1];
        float ad0 = sAd[col], ad1 = sAd[col + 1];
        float s_r0 = c0 * as0 + c1 * as1, d_r0 = c0 * ad0 + c1 * ad1;
        float s_r1 = c2 * as0 + c3 * as1, d_r1 = c2 * ad0 + c3 * ad1;
        if (nt < 8) { psA0 += s_r0; pdA0 += d_r0; psA1 += s_r1; pdA1 += d_r1; }
        else        { psB0 += s_r0; pdB0 += d_r0; psB1 += s_r1; pdB1 += d_r1; }
    }
#pragma unroll
    for (int o = 1; o <= 2; o <<= 1) {
        psA0 += __shfl_xor_sync(~0u, psA0, o); psB0 += __shfl_xor_sync(~0u, psB0, o);
        pdA0 += __shfl_xor_sync(~0u, pdA0, o); pdB0 += __shfl_xor_sync(~0u, pdB0, o);
        psA1 += __shfl_xor_sync(~0u, psA1, o); psB1 += __shfl_xor_sync(~0u, psB1, o);
        pdA1 += __shfl_xor_sync(~0u, pdA1, o); pdB1 += __shfl_xor_sync(~0u, pdB1, o);
    }
    if (q == 0) {
        if (n0 < N_NODES) {
            g_als[2 * n0] = psA0; g_als[2 * n0 + 1] = psB0;
            g_ald[2 * n0] = pdA0; g_ald[2 * n0 + 1] = pdB0;
        }
        if (n1 < N_NODES) {
            g_als[2 * n1] = psA1; g_als[2 * n1 + 1] = psB1;
            g_ald[2 * n1] = pdA1; g_ald[2 * n1 + 1] = pdB1;
        }
    }
}

// ---------------- gate MLP (8 nodes/warp, smem gw1) ----------------
__global__ void k_gate(const float* __restrict__ hout, const float* __restrict__ gw1,
                       const float* __restrict__ gb1, const float* __restrict__ gw2,
                       const float* __restrict__ gb2) {
    extern __shared__ float dsmf[];
    unsigned long long* sg = (unsigned long long*)dsmf;   // 32KB
    float* sh = dsmf + DC * 64;                           // 16KB
    int tid = threadIdx.x;
    int wl = tid >> 5, lane = tid & 31;
    {
        const unsigned long long* G = (const unsigned long long*)gw1;
        for (int i = tid; i < DC * 32; i += NTPB) sg[i] = G[i];
    }
    int nbase = (blockIdx.x * WPB + wl) * NPW;
    float* shw = sh + (size_t)wl * NPW * DC;
#pragma unroll
    for (int j = 0; j < NPW; j++) {
        int n = nbase + j;
        float4 v = (n < N_NODES) ? ((const float4*)hout)[(size_t)n * 32 + lane]
                                 : make_float4(0.f, 0.f, 0.f, 0.f);
        *(float4*)&shw[j * DC + lane * 4] = v;
    }
    __syncthreads();

    unsigned long long acc[NPW];
#pragma unroll
    for (int j = 0; j < NPW; j++) acc[j] = 0ull;
    for (int k = 0; k < DC; k += 4) {
        unsigned long long w0 = sg[(k + 0) * 32 + lane];
        unsigned long long w1 = sg[(k + 1) * 32 + lane];
        unsigned long long w2 = sg[(k + 2) * 32 + lane];
        unsigned long long w3 = sg[(k + 3) * 32 + lane];
#pragma unroll
        for (int j = 0; j < NPW; j++) {
            float4 h4 = *(const float4*)&shw[j * DC + k];
            fma2(acc[j], w0, pack2(h4.x));
            fma2(acc[j], w1, pack2(h4.y));
            fma2(acc[j], w2, pack2(h4.z));
            fma2(acc[j], w3, pack2(h4.w));
        }
    }

    float2 gb = __ldg((const float2*)gb1 + lane);
    float2 g2 = __ldg((const float2*)gw2 + lane);
    float gbias = __ldg(gb2);
#pragma unroll
    for (int j = 0; j < NPW; j++) {
        float2 u = unpack2(acc[j]);
        u.x = lrelu(u.x + gb.x, 0.05f);
        u.y = lrelu(u.y + gb.y, 0.05f);
        float ps = u.x * g2.x + u.y * g2.y;
        for (int o = 16; o; o >>= 1) ps += __shfl_xor_sync(~0u, ps, o);
        int n = nbase + j;
        if (lane == 0 && n < N_NODES) g_gate[n] = ps + gbias;
    }
}

// ---------------- per-graph softmax pooling + scratch re-zero for next call ----------------
__global__ void k_pool(const float* __restrict__ hout, float* __restrict__ zout) {
    int g = blockIdx.x;
    int t = threadIdx.x;
    int s = g_gptr[g], e = g_gptr[g + 1];
    __shared__ float red[128];
    __shared__ float wbuf[128];

    float lm = -3.4e38f;
    for (int i = s + t; i < e; i += 128) lm = fmaxf(lm, g_gate[i]);
    red[t] = lm;
    __syncthreads();
    for (int o = 64; o; o >>= 1) { if (t < o) red[t] = fmaxf(red[t], red[t + o]); __syncthreads(); }
    float gm = red[0];
    __syncthreads();

    float ls = 0.f;
    for (int i = s + t; i < e; i += 128) ls += __expf(g_gate[i] - gm);
    red[t] = ls;
    __syncthreads();
    for (int o = 64; o; o >>= 1) { if (t < o) red[t] += red[t + o]; __syncthreads(); }
    float inv = (e > s) ? 1.f / red[0] : 0.f;
    __syncthreads();

    float acc = 0.f;
    for (int base = s; base < e; base += 128) {
        int i = base + t;
        wbuf[t] = (i < e) ? __expf(g_gate[i] - gm) * inv : 0.f;
        __syncthreads();
        int cnt = min(128, e - base);
#pragma unroll 4
        for (int j = 0; j < cnt; j++)
            acc += wbuf[j] * hout[(size_t)(base + j) * DC + t];
        __syncthreads();
    }
    zout[g * DC + t] = acc;

    // re-zero histogram scratch for the next kernel_launch call (1024*128 >= N_NODES)
    int gid = g * 128 + t;
    if (gid < N_NODES) g_deg[gid] = 0;
    if (gid < N_GRAPH) g_gdeg[gid] = 0;
}

// ---------------- launch ----------------
extern "C" void kernel_launch(void* const* d_in, const int* in_sizes, int n_in,
                              void* d_out, int out_size) {
    const int*   x     = (const int*)d_in[0];
    const int*   ei    = (const int*)d_in[1];
    const int*   batch = (const int*)d_in[2];
    const float* emb   = (const float*)d_in[3];
    const float* lng   = (const float*)d_in[4];
    const float* lnb   = (const float*)d_in[5];
    const float* W1    = (const float*)d_in[6];
    const float* as1   = (const float*)d_in[7];
    const float* ad1   = (const float*)d_in[8];
    const float* b1    = (const float*)d_in[9];
    const float* W2    = (const float*)d_in[10];
    const float* as2   = (const float*)d_in[11];
    const float* ad2   = (const float*)d_in[12];
    const float* b2    = (const float*)d_in[13];
    const float* gw1   = (const float*)d_in[14];
    const float* gb1   = (const float*)d_in[15];
    const float* gw2   = (const float*)d_in[16];
    const float* gb2   = (const float*)d_in[17];
    float* out  = (float*)d_out;
    float* zout = out + (size_t)N_NODES * DC;

    const int node2_smem = 2 * 128 * PITCH_H * 2 + 2 * 128 * 4;   // ~70.7 KB
    const int gate_smem  = DC * 64 * 4 + WPB * NPW * DC * 4;      // 48 KB
    cudaFuncSetAttribute(k_node2m, cudaFuncAttributeMaxDynamicSharedMemorySize, node2_smem);
    cudaFuncSetAttribute(k_gate,   cudaFuncAttributeMaxDynamicSharedMemorySize, gate_smem);

    int nb_scan = (N_NODES + 1023) / 1024;

    // CSR build + graph segment pointers
    k_hist<<<(N_EDGES + 255) / 256, 256>>>(ei, batch);
    k_scan_block<<<nb_scan, 1024>>>();
    k_scan_add2<<<(N_NODES + 255) / 256, 256>>>(nb_scan);
    k_scatter<<<(N_EDGES + 255) / 256, 256>>>(ei);
    k_rowsortw<<<(N_NODES + WPB - 1) / WPB, NTPB>>>();

    int nb_agg  = (N_NODES + WPB - 1) / WPB;
    int nb_blk  = (N_NODES + WPB * NPW - 1) / (WPB * NPW);
    int nb_edge = (N_EDGES + 255) / 256;
    int nb_mma  = (N_NODES + 127) / 128;

    k_node1<<<nb_blk, NTPB>>>(x, emb, lng, lnb, W1, as1, ad1);
    k_elog<<<nb_edge, 256>>>();
    k_agg<<<nb_agg, NTPB>>>(b1, nullptr, 1);
    k_node2m<<<nb_mma, NTPB, node2_smem>>>(W2, as2, ad2);
    k_elog<<<nb_edge, 256>>>();
    k_agg<<<nb_agg, NTPB>>>(b2, out, 2);
    k_gate<<<nb_blk, NTPB, gate_smem>>>(out, gw1, gb1, gw2, gb2);
    k_pool<<<N_GRAPH, 128>>>(out, zout);
}

// round 13
// speedup vs baseline: 1.8388x; 1.0888x over previous
#include <cuda_runtime.h>
#include <cuda_fp16.h>

#define N_NODES 100000
#define N_EDGES 1600000
#define N_GRAPH 1024
#define EMB 32
#define DC 128
#define WPB 8       // warps per block
#define NPW 8       // nodes per warp (register blocking in dense kernels)
#define NTPB 256

// ---------------- scratch (static device globals; no allocation) ----------------
__device__ int    g_deg[N_NODES];        // zeroed by k_pool of previous run (init: BSS zero)
__device__ int    g_rowptr[N_NODES + 1];
__device__ int    g_cursor[N_NODES];
__device__ int2   g_sd[N_EDGES];         // {src, dst} per CSR slot
__device__ int    g_bsums[256];
__device__ int    g_gdeg[N_GRAPH];       // zeroed by k_pool of previous run
__device__ int    g_gptr[N_GRAPH + 1];
__device__ __half g_xwh[(size_t)N_NODES * DC];   // fp16 message payload
__device__ __half g_h1h[(size_t)N_NODES * DC];   // fp16 h (layer-1 for node2, layer-2 for gate)
__device__ float  g_als[N_NODES * 2];
__device__ float  g_ald[N_NODES * 2];
__device__ float  g_elog[(size_t)N_EDGES * 2];   // EXP of logits
__device__ float  g_gate[N_NODES];

__device__ __forceinline__ float lrelu(float x, float s) { return x > 0.f ? x : s * x; }

// f32x2 packed helpers (sm_103a; ptxas never emits FFMA2 from C++)
__device__ __forceinline__ unsigned long long pack2(float v) {
    unsigned long long r; asm("mov.b64 %0,{%1,%1};" : "=l"(r) : "f"(v)); return r;
}
__device__ __forceinline__ void fma2(unsigned long long& a, unsigned long long x, unsigned long long p) {
    asm("fma.rn.f32x2 %0,%1,%2,%0;" : "+l"(a) : "l"(x), "l"(p));
}
__device__ __forceinline__ float2 unpack2(unsigned long long v) {
    float2 r; asm("mov.b64 {%0,%1},%2;" : "=f"(r.x), "=f"(r.y) : "l"(v)); return r;
}

// store 4 fp32 as 4 fp16 in one 8B write
__device__ __forceinline__ void store_h4(__half* row, int lane, float a, float b, float c, float d) {
    union { uint2 u; __half2 h[2]; } cv;
    cv.h[0] = __float22half2_rn(make_float2(a, b));
    cv.h[1] = __float22half2_rn(make_float2(c, d));
    ((uint2*)row)[lane] = cv.u;
}

// 8 halfs (uint4) * p accumulated into 8 fp32
__device__ __forceinline__ void h8_fma(float* acc, uint4 v, float p) {
    union { unsigned u; __half2 h; } c;
    float2 f;
    c.u = v.x; f = __half22float2(c.h); acc[0] += f.x * p; acc[1] += f.y * p;
    c.u = v.y; f = __half22float2(c.h); acc[2] += f.x * p; acc[3] += f.y * p;
    c.u = v.z; f = __half22float2(c.h); acc[4] += f.x * p; acc[5] += f.y * p;
    c.u = v.w; f = __half22float2(c.h); acc[6] += f.x * p; acc[7] += f.y * p;
}

__device__ __forceinline__ unsigned s2u(const void* p) {
    unsigned a;
    asm("{.reg .u64 t; cvta.to.shared.u64 t,%1; cvt.u32.u64 %0,t;}" : "=r"(a) : "l"(p));
    return a;
}

#define LDSM4(r0, r1, r2, r3, addr) \
    asm volatile("ldmatrix.sync.aligned.m8n8.x4.shared.b16 {%0,%1,%2,%3},[%4];" \
                 : "=r"(r0), "=r"(r1), "=r"(r2), "=r"(r3) : "r"(addr))
#define LDSM4T(r0, r1, r2, r3, addr) \
    asm volatile("ldmatrix.sync.aligned.m8n8.x4.trans.shared.b16 {%0,%1,%2,%3},[%4];" \
                 : "=r"(r0), "=r"(r1), "=r"(r2), "=r"(r3) : "r"(addr))
#define MMA16816(C, a0, a1, a2, a3, b0, b1) \
    asm volatile("mma.sync.aligned.m16n8k16.row.col.f32.f16.f16.f32 " \
                 "{%0,%1,%2,%3},{%4,%5,%6,%7},{%8,%9},{%0,%1,%2,%3};" \
                 : "+f"((C)[0]), "+f"((C)[1]), "+f"((C)[2]), "+f"((C)[3]) \
                 : "r"(a0), "r"(a1), "r"(a2), "r"(a3), "r"(b0), "r"(b1))

// ---------------- CSR build ----------------
__global__ void k_hist(const int* __restrict__ ei, const int* __restrict__ batch) {
    int i = blockIdx.x * blockDim.x + threadIdx.x;
    if (i < N_EDGES) atomicAdd(&g_deg[ei[N_EDGES + i]], 1);
    if (i < N_NODES) atomicAdd(&g_gdeg[batch[i]], 1);
}

__global__ void k_scan_block() {
    __shared__ int sh[1024];
    int t = threadIdx.x;
    int i = blockIdx.x * 1024 + t;
    int v = (i < N_NODES) ? g_deg[i] : 0;
    sh[t] = v;
    __syncthreads();
    for (int off = 1; off < 1024; off <<= 1) {
        int a = (t >= off) ? sh[t - off] : 0;
        __syncthreads();
        sh[t] += a;
        __syncthreads();
    }
    if (i < N_NODES) g_rowptr[i] = sh[t] - v;
    if (t == 1023) g_bsums[blockIdx.x] = sh[1023];
}

// fused: block-sum scan + add + cursor init + total; last block also builds g_gptr
__global__ void k_scan_add2(int nb) {
    __shared__ int sb[128];
    int t = threadIdx.x;
    if (t < 128) sb[t] = (t < nb) ? g_bsums[t] : 0;
    __syncthreads();
    for (int off = 1; off < 128; off <<= 1) {
        int a = (t < 128 && t >= off) ? sb[t - off] : 0;
        __syncthreads();
        if (t < 128) sb[t] += a;
        __syncthreads();
    }
    int i = blockIdx.x * blockDim.x + t;
    if (i < N_NODES) {
        int b = i >> 10;
        int vv = g_rowptr[i] + (b ? sb[b - 1] : 0);
        g_rowptr[i] = vv;
        g_cursor[i] = vv;
    }
    if (i == 0) g_rowptr[N_NODES] = sb[nb - 1];

    if (blockIdx.x == gridDim.x - 1) {    // graph-pointer scan (1024 entries, 4/thread)
        __shared__ int gs[256];
        int b4 = t * 4;
        int a0 = g_gdeg[b4], a1 = g_gdeg[b4 + 1], a2 = g_gdeg[b4 + 2], a3 = g_gdeg[b4 + 3];
        int tot = a0 + a1 + a2 + a3;
        gs[t] = tot;
        __syncthreads();
        for (int off = 1; off < 256; off <<= 1) {
            int a = (t >= off) ? gs[t - off] : 0;
            __syncthreads();
            gs[t] += a;
            __syncthreads();
        }
        int excl = gs[t] - tot;
        g_gptr[b4]     = excl;
        g_gptr[b4 + 1] = excl + a0;
        g_gptr[b4 + 2] = excl + a0 + a1;
        g_gptr[b4 + 3] = excl + a0 + a1 + a2;
        if (t == 255) g_gptr[N_GRAPH] = gs[255];
    }
}

__global__ void k_scatter(const int* __restrict__ ei) {
    int i = blockIdx.x * blockDim.x + threadIdx.x;
    if (i >= N_EDGES) return;
    int s = ei[i];
    int d = ei[N_EDGES + i];
    int pos = atomicAdd(&g_cursor[d], 1);
    g_sd[pos] = make_int2(s, d);
}

// warp-per-node sort of src keys (dst is row-constant, stays in place)
__global__ void k_rowsortw() {
    __shared__ int buf[WPB][160];
    int wl = threadIdx.x >> 5, lane = threadIdx.x & 31;
    int n = blockIdx.x * WPB + wl;
    if (n >= N_NODES) return;
    int rs = g_rowptr[n], L = g_rowptr[n + 1] - rs;
    if (L <= 1) return;
    if (L <= 32) {
        int v = (lane < L) ? g_sd[rs + lane].x : 0x7fffffff;
#pragma unroll
        for (int k = 2; k <= 32; k <<= 1) {
#pragma unroll
            for (int j = k >> 1; j; j >>= 1) {
                int o = __shfl_xor_sync(~0u, v, j);
                bool up = ((lane & k) == 0);
                bool lo = ((lane & j) == 0);
                v = (up == lo) ? min(v, o) : max(v, o);
            }
        }
        if (lane < L) g_sd[rs + lane].x = v;
    } else if (L <= 64) {
        int i0 = lane, i1 = lane + 32;
        int v0 = (i0 < L) ? g_sd[rs + i0].x : 0x7fffffff;
        int v1 = (i1 < L) ? g_sd[rs + i1].x : 0x7fffffff;
#pragma unroll
        for (int k = 2; k <= 64; k <<= 1) {
#pragma unroll
            for (int j = k >> 1; j; j >>= 1) {
                if (j >= 32) {
                    int lo = min(v0, v1), hi = max(v0, v1);
                    v0 = lo; v1 = hi;
                } else {
                    int o0 = __shfl_xor_sync(~0u, v0, j);
                    int o1 = __shfl_xor_sync(~0u, v1, j);
                    bool up0 = ((i0 & k) == 0), up1 = ((i1 & k) == 0);
                    bool lo0 = ((i0 & j) == 0), lo1 = ((i1 & j) == 0);
                    v0 = (up0 == lo0) ? min(v0, o0) : max(v0, o0);
                    v1 = (up1 == lo1) ? min(v1, o1) : max(v1, o1);
                }
            }
        }
        if (i0 < L) g_sd[rs + i0].x = v0;
        if (i1 < L) g_sd[rs + i1].x = v1;
    } else if (L <= 160) {
        for (int i = lane; i < L; i += 32) buf[wl][i] = g_sd[rs + i].x;
        __syncwarp();
        for (int p = 0; p < L; p++) {
            for (int i = (p & 1) + 2 * lane; i + 1 < L; i += 64) {
                int a = buf[wl][i], b = buf[wl][i + 1];
                if (a > b) { buf[wl][i] = b; buf[wl][i + 1] = a; }
            }
            __syncwarp();
        }
        for (int i = lane; i < L; i += 32) g_sd[rs + i].x = buf[wl][i];
    } else if (lane == 0) {
        int re = rs + L;
        for (int i = rs + 1; i < re; i++) {
            int key = g_sd[i].x;
            int j = i - 1;
            while (j >= rs && g_sd[j].x > key) { g_sd[j + 1].x = g_sd[j].x; j--; }
            g_sd[j + 1].x = key;
        }
    }
}

// ---------------- layer 1: embed + LN + W1 + logits (8 nodes/warp, f32x2) ----------------
__global__ void k_node1(const int* __restrict__ x, const float* __restrict__ emb,
                        const float* __restrict__ lng, const float* __restrict__ lnb,
                        const float* __restrict__ W1, const float* __restrict__ asr,
                        const float* __restrict__ adt) {
    __shared__ ulonglong2 sW[EMB * 32];
    __shared__ float sxn[WPB][NPW][EMB];
    int tid = threadIdx.x;
    int wl = tid >> 5, lane = tid & 31;
    {
        const ulonglong2* W4 = (const ulonglong2*)W1;
        for (int i = tid; i < EMB * 32; i += NTPB) sW[i] = W4[i];
    }
    int nbase = (blockIdx.x * WPB + wl) * NPW;

#pragma unroll
    for (int j = 0; j < NPW; j++) {
        int n = nbase + j;
        float xn = 0.f;
        if (n < N_NODES) {
            int vi = x[n];
            float xv = emb[vi * EMB + lane];
            float m = xv;
            for (int o = 16; o; o >>= 1) m += __shfl_xor_sync(~0u, m, o);
            m *= (1.f / EMB);
            float dv = xv - m;
            float var = dv * dv;
            for (int o = 16; o; o >>= 1) var += __shfl_xor_sync(~0u, var, o);
            var *= (1.f / EMB);
            xn = dv * rsqrtf(var + 1e-5f) * lng[lane] + lnb[lane];
        }
        sxn[wl][j][lane] = xn;
    }
    __syncthreads();

    unsigned long long accA[NPW], accB[NPW];
#pragma unroll
    for (int j = 0; j < NPW; j++) { accA[j] = 0ull; accB[j] = 0ull; }
#pragma unroll
    for (int k = 0; k < EMB; k += 4) {
        ulonglong2 w0 = sW[(k + 0) * 32 + lane];
        ulonglong2 w1 = sW[(k + 1) * 32 + lane];
        ulonglong2 w2 = sW[(k + 2) * 32 + lane];
        ulonglong2 w3 = sW[(k + 3) * 32 + lane];
#pragma unroll
        for (int j = 0; j < NPW; j++) {
            float4 h4 = *(const float4*)&sxn[wl][j][k];
            unsigned long long p;
            p = pack2(h4.x); fma2(accA[j], w0.x, p); fma2(accB[j], w0.y, p);
            p = pack2(h4.y); fma2(accA[j], w1.x, p); fma2(accB[j], w1.y, p);
            p = pack2(h4.z); fma2(accA[j], w2.x, p); fma2(accB[j], w2.y, p);
            p = pack2(h4.w); fma2(accA[j], w3.x, p); fma2(accB[j], w3.y, p);
        }
    }

    float4 as4 = __ldg((const float4*)asr + lane);
    float4 ad4 = __ldg((const float4*)adt + lane);
#pragma unroll
    for (int j = 0; j < NPW; j++) {
        int n = nbase + j;
        float2 lo = unpack2(accA[j]), hi = unpack2(accB[j]);
        float ps = lo.x * as4.x + lo.y * as4.y + hi.x * as4.z + hi.y * as4.w;
        float pd = lo.x * ad4.x + lo.y * ad4.y + hi.x * ad4.z + hi.y * ad4.w;
        for (int o = 8; o; o >>= 1) {
            ps += __shfl_xor_sync(~0u, ps, o);
            pd += __shfl_xor_sync(~0u, pd, o);
        }
        if (n < N_NODES) {
            store_h4(g_xwh + (size_t)n * DC, lane, lo.x, lo.y, hi.x, hi.y);
            if ((lane & 15) == 0) {
                int h = lane >> 4;
                g_als[n * 2 + h] = ps;
                g_ald[n * 2 + h] = pd;
            }
        }
    }
}

// ---------------- edge-parallel: exp(lrelu(logit)) precompute ----------------
__global__ void k_elog() {
    int p = blockIdx.x * blockDim.x + threadIdx.x;
    if (p >= N_EDGES) return;
    int2 sd = g_sd[p];
    float2 a = __ldg((const float2*)g_als + sd.x);
    float2 b = __ldg((const float2*)g_ald + sd.y);
    ((float2*)g_elog)[p] = make_float2(__expf(lrelu(a.x + b.x, 0.2f)),
                                       __expf(lrelu(a.y + b.y, 0.2f)));
}

// ---------------- GAT aggregation: warp/node, register-staged row ----------------
__global__ void k_agg(const float* __restrict__ bias, float* __restrict__ out2, int layer) {
    int n = blockIdx.x * WPB + (threadIdx.x >> 5);
    int lane = threadIdx.x & 31;
    if (n >= N_NODES) return;

    int rs = g_rowptr[n], re = g_rowptr[n + 1];
    int L = re - rs;
    float2 a = *(const float2*)&g_als[2 * n];
    float2 b = *(const float2*)&g_ald[2 * n];
    float ps0 = __expf(lrelu(a.x + b.x, 0.2f));
    float ps1 = __expf(lrelu(a.y + b.y, 0.2f));

    int half  = lane >> 4;
    int s16   = lane & 15;
    int headb = s16 >> 3;

    float acc[8];
    {
        float pself = (half == 0) ? (headb ? ps1 : ps0) : 0.f;
        uint4 xs = __ldg((const uint4*)(g_xwh + (size_t)n * DC) + s16);
#pragma unroll
        for (int i = 0; i < 8; i++) acc[i] = 0.f;
        h8_fma(acc, xs, pself);
    }

    float s0, s1;
    if (L <= 32) {
        int   src_l = (lane < L) ? __ldg(&g_sd[rs + lane].x) : 0;
        float2 e_l  = (lane < L) ? __ldg((const float2*)g_elog + rs + lane)
                                 : make_float2(0.f, 0.f);
        s0 = e_l.x; s1 = e_l.y;
#pragma unroll
        for (int o = 16; o; o >>= 1) {
            s0 += __shfl_xor_sync(~0u, s0, o);
            s1 += __shfl_xor_sync(~0u, s1, o);
        }
#pragma unroll 4
        for (int j = 0; j < L; j += 2) {
            int jj = (j + half) & 31;
            int srcj = __shfl_sync(~0u, src_l, jj);
            float px = __shfl_sync(~0u, e_l.x, jj);
            float py = __shfl_sync(~0u, e_l.y, jj);
            float p = (j + half < L) ? (headb ? py : px) : 0.f;
            uint4 xv = __ldg((const uint4*)(g_xwh + (size_t)srcj * DC) + s16);
            h8_fma(acc, xv, p);
        }
    } else {
        s0 = 0.f; s1 = 0.f;
        for (int k = rs + lane; k < re; k += 32) {
            float2 e2 = __ldg((const float2*)g_elog + k);
            s0 += e2.x;
            s1 += e2.y;
        }
#pragma unroll
        for (int o = 16; o; o >>= 1) {
            s0 += __shfl_xor_sync(~0u, s0, o);
            s1 += __shfl_xor_sync(~0u, s1, o);
        }
#pragma unroll 4
        for (int k = rs; k < re; k += 2) {
            int kk = k + half;
            int kc = kk < re ? kk : re - 1;
            int src = __ldg(&g_sd[kc].x);
            float2 e2 = __ldg((const float2*)g_elog + kc);
            float p = (kk < re) ? (headb ? e2.y : e2.x) : 0.f;
            uint4 xv = __ldg((const uint4*)(g_xwh + (size_t)src * DC) + s16);
            h8_fma(acc, xv, p);
        }
    }

#pragma unroll
    for (int i = 0; i < 8; i++) acc[i] += __shfl_xor_sync(~0u, acc[i], 16);

    float inv0 = 1.f / (s0 + ps0);
    float inv1 = 1.f / (s1 + ps1);
    float invh = headb ? inv1 : inv0;
    int idx = s16 * 2 + half;
    float4 bi = __ldg((const float4*)bias + idx);
    const float* ap = acc + half * 4;
    float4 o;
    o.x = ap[0] * invh + bi.x;
    o.y = ap[1] * invh + bi.y;
    o.z = ap[2] * invh + bi.z;
    o.w = ap[3] * invh + bi.w;
    if (layer == 1) {
        o.x = lrelu(o.x, 0.05f); o.y = lrelu(o.y, 0.05f);
        o.z = lrelu(o.z, 0.05f); o.w = lrelu(o.w, 0.05f);
        store_h4(g_h1h + (size_t)n * DC, idx, o.x, o.y, o.z, o.w);   // fp16 for MMA node2
    } else {
        ((float4*)out2)[(size_t)n * 32 + idx] = o;                   // fp32 h output
        store_h4(g_h1h + (size_t)n * DC, idx, o.x, o.y, o.z, o.w);   // fp16 for MMA gate
    }
}

// ---------------- layer 2 node transform via HMMA: h1h @ W2 + logits ----------------
// block: 256 thr / 8 warps; warp computes 16 nodes x 128 dims; smem A+B padded pitch 272B.
#define PITCH_H 136   // halfs per smem row (128 + 8 pad)
__global__ void k_node2m(const float* __restrict__ W2, const float* __restrict__ asr,
                         const float* __restrict__ adt) {
    extern __shared__ char dsm[];
    __half* sA = (__half*)dsm;                                 // 128 x PITCH_H
    __half* sB = (__half*)(dsm + 128 * PITCH_H * 2);           // 128 x PITCH_H
    float*  sAs = (float*)(dsm + 2 * 128 * PITCH_H * 2);       // 128
    float*  sAd = sAs + 128;

    int tid = threadIdx.x;
    int wl = tid >> 5, lane = tid & 31;
    int bb = blockIdx.x * 128;

    if (tid < 128) { sAs[tid] = asr[tid]; sAd[tid] = adt[tid]; }
    // stage B: W2 fp32 -> fp16
    for (int i = tid; i < 128 * 64; i += NTPB) {
        int k = i >> 6, c2 = i & 63;
        float2 w = *(const float2*)(W2 + k * 128 + c2 * 2);
        *(__half2*)(sB + k * PITCH_H + c2 * 2) = __float22half2_rn(w);
    }
    // stage A: g_h1h rows
    for (int i = tid; i < 128 * 16; i += NTPB) {
        int r = i >> 4, c = i & 15;
        int rg = bb + r; if (rg >= N_NODES) rg = N_NODES - 1;
        uint4 v = *(const uint4*)(g_h1h + (size_t)rg * DC + c * 8);
        *(uint4*)(sA + r * PITCH_H + c * 8) = v;
    }
    __syncthreads();

    float C[16][4];
#pragma unroll
    for (int t = 0; t < 16; t++) { C[t][0] = 0.f; C[t][1] = 0.f; C[t][2] = 0.f; C[t][3] = 0.f; }

    int g = lane >> 3;
    int rrow = (lane & 7) + ((g & 1) << 3);
    unsigned aBase = s2u(sA + wl * 16 * PITCH_H) + rrow * (PITCH_H * 2) + ((g >> 1) << 4);
    unsigned bBase = s2u(sB) + rrow * (PITCH_H * 2) + ((g >> 1) << 4);

#pragma unroll
    for (int kg = 0; kg < 8; kg++) {
        unsigned a0, a1, a2, a3;
        LDSM4(a0, a1, a2, a3, aBase + kg * 32);
#pragma unroll
        for (int nt = 0; nt < 8; nt++) {
            unsigned b0, b1, b2, b3;
            LDSM4T(b0, b1, b2, b3, bBase + kg * 16 * (PITCH_H * 2) + nt * 32);
            MMA16816(C[nt * 2],     a0, a1, a2, a3, b0, b1);
            MMA16816(C[nt * 2 + 1], a0, a1, a2, a3, b2, b3);
        }
    }

    // epilogue: store fp16 payload + logits
    int q = lane & 3;
    int r0 = wl * 16 + (lane >> 2);
    int n0 = bb + r0, n1 = n0 + 8;
    float psA0 = 0.f, psB0 = 0.f, pdA0 = 0.f, pdB0 = 0.f;
    float psA1 = 0.f, psB1 = 0.f, pdA1 = 0.f, pdB1 = 0.f;
#pragma unroll
    for (int nt = 0; nt < 16; nt++) {
        int col = nt * 8 + q * 2;
        float c0 = C[nt][0], c1 = C[nt][1], c2 = C[nt][2], c3 = C[nt][3];
        if (n0 < N_NODES)
            *(__half2*)(g_xwh + (size_t)n0 * DC + col) = __floats2half2_rn(c0, c1);
        if (n1 < N_NODES)
            *(__half2*)(g_xwh + (size_t)n1 * DC + col) = __floats2half2_rn(c2, c3);
        float as0 = sAs[col], as1 = sAs[col + 1];
        float ad0 = sAd[col], ad1 = sAd[col + 1];
        float s_r0 = c0 * as0 + c1 * as1, d_r0 = c0 * ad0 + c1 * ad1;
        float s_r1 = c2 * as0 + c3 * as1, d_r1 = c2 * ad0 + c3 * ad1;
        if (nt < 8) { psA0 += s_r0; pdA0 += d_r0; psA1 += s_r1; pdA1 += d_r1; }
        else        { psB0 += s_r0; pdB0 += d_r0; psB1 += s_r1; pdB1 += d_r1; }
    }
#pragma unroll
    for (int o = 1; o <= 2; o <<= 1) {
        psA0 += __shfl_xor_sync(~0u, psA0, o); psB0 += __shfl_xor_sync(~0u, psB0, o);
        pdA0 += __shfl_xor_sync(~0u, pdA0, o); pdB0 += __shfl_xor_sync(~0u, pdB0, o);
        psA1 += __shfl_xor_sync(~0u, psA1, o); psB1 += __shfl_xor_sync(~0u, psB1, o);
        pdA1 += __shfl_xor_sync(~0u, pdA1, o); pdB1 += __shfl_xor_sync(~0u, pdB1, o);
    }
    if (q == 0) {
        if (n0 < N_NODES) {
            g_als[2 * n0] = psA0; g_als[2 * n0 + 1] = psB0;
            g_ald[2 * n0] = pdA0; g_ald[2 * n0 + 1] = pdB0;
        }
        if (n1 < N_NODES) {
            g_als[2 * n1] = psA1; g_als[2 * n1 + 1] = psB1;
            g_ald[2 * n1] = pdA1; g_ald[2 * n1 + 1] = pdB1;
        }
    }
}

// ---------------- gate MLP via HMMA: h(fp16) @ gw1 -> lrelu -> @ gw2 ----------------
#define PB_G 72   // halfs per smem row for gw1 tile (64 + 8 pad)
__global__ void k_gatem(const float* __restrict__ gw1, const float* __restrict__ gb1,
                        const float* __restrict__ gw2, const float* __restrict__ gb2) {
    extern __shared__ char dsm[];
    __half* sA = (__half*)dsm;                                 // 128 x PITCH_H (h rows)
    __half* sB = (__half*)(dsm + 128 * PITCH_H * 2);           // 128 x PB_G (gw1)
    float*  sGb = (float*)(dsm + 128 * PITCH_H * 2 + 128 * PB_G * 2);  // 64
    float*  sGw = sGb + 64;                                    // 64

    int tid = threadIdx.x;
    int wl = tid >> 5, lane = tid & 31;
    int bb = blockIdx.x * 128;

    if (tid < 64) { sGb[tid] = gb1[tid]; sGw[tid] = gw2[tid]; }
    // stage B: gw1 (128x64) fp32 -> fp16
    for (int i = tid; i < 128 * 32; i += NTPB) {
        int k = i >> 5, c2 = i & 31;
        float2 w = *(const float2*)(gw1 + k * 64 + c2 * 2);
        *(__half2*)(sB + k * PB_G + c2 * 2) = __float22half2_rn(w);
    }
    // stage A: g_h1h rows (layer-2 h, fp16)
    for (int i = tid; i < 128 * 16; i += NTPB) {
        int r = i >> 4, c = i & 15;
        int rg = bb + r; if (rg >= N_NODES) rg = N_NODES - 1;
        uint4 v = *(const uint4*)(g_h1h + (size_t)rg * DC + c * 8);
        *(uint4*)(sA + r * PITCH_H + c * 8) = v;
    }
    __syncthreads();

    float C[8][4];
#pragma unroll
    for (int t = 0; t < 8; t++) { C[t][0] = 0.f; C[t][1] = 0.f; C[t][2] = 0.f; C[t][3] = 0.f; }

    int g = lane >> 3;
    int rrow = (lane & 7) + ((g & 1) << 3);
    unsigned aBase = s2u(sA + wl * 16 * PITCH_H) + rrow * (PITCH_H * 2) + ((g >> 1) << 4);
    unsigned bBase = s2u(sB) + rrow * (PB_G * 2) + ((g >> 1) << 4);

#pragma unroll
    for (int kg = 0; kg < 8; kg++) {
        unsigned a0, a1, a2, a3;
        LDSM4(a0, a1, a2, a3, aBase + kg * 32);
#pragma unroll
        for (int nt = 0; nt < 4; nt++) {
            unsigned b0, b1, b2, b3;
            LDSM4T(b0, b1, b2, b3, bBase + kg * 16 * (PB_G * 2) + nt * 32);
            MMA16816(C[nt * 2],     a0, a1, a2, a3, b0, b1);
            MMA16816(C[nt * 2 + 1], a0, a1, a2, a3, b2, b3);
        }
    }

    // epilogue: u = lrelu(C + gb1); gate = u . gw2 (+gb2)
    int q = lane & 3;
    int r0 = wl * 16 + (lane >> 2);
    int n0 = bb + r0, n1 = n0 + 8;
    float g0 = 0.f, g1 = 0.f;
#pragma unroll
    for (int nt = 0; nt < 8; nt++) {
        int col = nt * 8 + q * 2;
        float b0 = sGb[col], b1 = sGb[col + 1];
        float w0 = sGw[col], w1 = sGw[col + 1];
        g0 += lrelu(C[nt][0] + b0, 0.05f) * w0 + lrelu(C[nt][1] + b1, 0.05f) * w1;
        g1 += lrelu(C[nt][2] + b0, 0.05f) * w0 + lrelu(C[nt][3] + b1, 0.05f) * w1;
    }
#pragma unroll
    for (int o = 1; o <= 2; o <<= 1) {
        g0 += __shfl_xor_sync(~0u, g0, o);
        g1 += __shfl_xor_sync(~0u, g1, o);
    }
    if (q == 0) {
        float gbias = *gb2;
        if (n0 < N_NODES) g_gate[n0] = g0 + gbias;
        if (n1 < N_NODES) g_gate[n1] = g1 + gbias;
    }
}

// ---------------- per-graph softmax pooling + scratch re-zero for next call ----------------
__global__ void k_pool(const float* __restrict__ hout, float* __restrict__ zout) {
    int g = blockIdx.x;
    int t = threadIdx.x;
    int s = g_gptr[g], e = g_gptr[g + 1];
    __shared__ float red[128];
    __shared__ float wbuf[128];

    float lm = -3.4e38f;
    for (int i = s + t; i < e; i += 128) lm = fmaxf(lm, g_gate[i]);
    red[t] = lm;
    __syncthreads();
    for (int o = 64; o; o >>= 1) { if (t < o) red[t] = fmaxf(red[t], red[t + o]); __syncthreads(); }
    float gm = red[0];
    __syncthreads();

    float ls = 0.f;
    for (int i = s + t; i < e; i += 128) ls += __expf(g_gate[i] - gm);
    red[t] = ls;
    __syncthreads();
    for (int o = 64; o; o >>= 1) { if (t < o) red[t] += red[t + o]; __syncthreads(); }
    float inv = (e > s) ? 1.f / red[0] : 0.f;
    __syncthreads();

    float acc = 0.f;
    for (int base = s; base < e; base += 128) {
        int i = base + t;
        wbuf[t] = (i < e) ? __expf(g_gate[i] - gm) * inv : 0.f;
        __syncthreads();
        int cnt = min(128, e - base);
#pragma unroll 4
        for (int j = 0; j < cnt; j++)
            acc += wbuf[j] * hout[(size_t)(base + j) * DC + t];
        __syncthreads();
    }
    zout[g * DC + t] = acc;

    // re-zero histogram scratch for the next kernel_launch call (1024*128 >= N_NODES)
    int gid = g * 128 + t;
    if (gid < N_NODES) g_deg[gid] = 0;
    if (gid < N_GRAPH) g_gdeg[gid] = 0;
}

// ---------------- launch ----------------
extern "C" void kernel_launch(void* const* d_in, const int* in_sizes, int n_in,
                              void* d_out, int out_size) {
    const int*   x     = (const int*)d_in[0];
    const int*   ei    = (const int*)d_in[1];
    const int*   batch = (const int*)d_in[2];
    const float* emb   = (const float*)d_in[3];
    const float* lng   = (const float*)d_in[4];
    const float* lnb   = (const float*)d_in[5];
    const float* W1    = (const float*)d_in[6];
    const float* as1   = (const float*)d_in[7];
    const float* ad1   = (const float*)d_in[8];
    const float* b1    = (const float*)d_in[9];
    const float* W2    = (const float*)d_in[10];
    const float* as2   = (const float*)d_in[11];
    const float* ad2   = (const float*)d_in[12];
    const float* b2    = (const float*)d_in[13];
    const float* gw1   = (const float*)d_in[14];
    const float* gb1   = (const float*)d_in[15];
    const float* gw2   = (const float*)d_in[16];
    const float* gb2   = (const float*)d_in[17];
    float* out  = (float*)d_out;
    float* zout = out + (size_t)N_NODES * DC;

    const int node2_smem = 2 * 128 * PITCH_H * 2 + 2 * 128 * 4;               // ~70.7 KB
    const int gate_smem  = 128 * PITCH_H * 2 + 128 * PB_G * 2 + 2 * 64 * 4;   // ~53.8 KB
    cudaFuncSetAttribute(k_node2m, cudaFuncAttributeMaxDynamicSharedMemorySize, node2_smem);
    cudaFuncSetAttribute(k_gatem,  cudaFuncAttributeMaxDynamicSharedMemorySize, gate_smem);

    int nb_scan = (N_NODES + 1023) / 1024;

    // CSR build + graph segment pointers
    k_hist<<<(N_EDGES + 255) / 256, 256>>>(ei, batch);
    k_scan_block<<<nb_scan, 1024>>>();
    k_scan_add2<<<(N_NODES + 255) / 256, 256>>>(nb_scan);
    k_scatter<<<(N_EDGES + 255) / 256, 256>>>(ei);
    k_rowsortw<<<(N_NODES + WPB - 1) / WPB, NTPB>>>();

    int nb_agg  = (N_NODES + WPB - 1) / WPB;
    int nb_blk  = (N_NODES + WPB * NPW - 1) / (WPB * NPW);
    int nb_edge = (N_EDGES + 255) / 256;
    int nb_mma  = (N_NODES + 127) / 128;

    k_node1<<<nb_blk, NTPB>>>(x, emb, lng, lnb, W1, as1, ad1);
    k_elog<<<nb_edge, 256>>>();
    k_agg<<<nb_agg, NTPB>>>(b1, nullptr, 1);
    k_node2m<<<nb_mma, NTPB, node2_smem>>>(W2, as2, ad2);
    k_elog<<<nb_edge, 256>>>();
    k_agg<<<nb_agg, NTPB>>>(b2, out, 2);
    k_gatem<<<nb_mma, NTPB, gate_smem>>>(gw1, gb1, gw2, gb2);
    k_pool<<<N_GRAPH, 128>>>(out, zout);
}

// round 15
// speedup vs baseline: 1.8809x; 1.0229x over previous
#include <cuda_runtime.h>
#include <cuda_fp16.h>

#define N_NODES 100000
#define N_EDGES 1600000
#define N_GRAPH 1024
#define EMB 32
#define DC 128
#define WPB 8       // warps per block
#define NPW 8       // nodes per warp (register blocking in dense kernels)
#define NTPB 256

// ---------------- scratch (static device globals; no allocation) ----------------
__device__ int    g_deg[N_NODES];        // zeroed by k_pool of previous run (init: BSS zero)
__device__ int    g_rowptr[N_NODES + 1];
__device__ int    g_cursor[N_NODES];
__device__ int2   g_sd[N_EDGES];         // {src, dst} per CSR slot
__device__ int    g_bsums[256];
__device__ int    g_gdeg[N_GRAPH];       // zeroed by k_pool of previous run
__device__ int    g_gptr[N_GRAPH + 1];
__device__ __half g_xwh[(size_t)N_NODES * DC];   // fp16 message payload
__device__ __half g_h1h[(size_t)N_NODES * DC];   // fp16 h (layer-1 for node2, layer-2 for gate/pool)
__device__ float  g_als[N_NODES * 2];
__device__ float  g_ald[N_NODES * 2];
__device__ uint4  g_pk[N_EDGES];         // packed {src, exp0_bits, exp1_bits, 0}
__device__ float  g_gate[N_NODES];

__device__ __forceinline__ float lrelu(float x, float s) { return x > 0.f ? x : s * x; }

// f32x2 packed helpers (sm_103a; ptxas never emits FFMA2 from C++)
__device__ __forceinline__ unsigned long long pack2(float v) {
    unsigned long long r; asm("mov.b64 %0,{%1,%1};" : "=l"(r) : "f"(v)); return r;
}
__device__ __forceinline__ void fma2(unsigned long long& a, unsigned long long x, unsigned long long p) {
    asm("fma.rn.f32x2 %0,%1,%2,%0;" : "+l"(a) : "l"(x), "l"(p));
}
__device__ __forceinline__ float2 unpack2(unsigned long long v) {
    float2 r; asm("mov.b64 {%0,%1},%2;" : "=f"(r.x), "=f"(r.y) : "l"(v)); return r;
}

// store 4 fp32 as 4 fp16 in one 8B write
__device__ __forceinline__ void store_h4(__half* row, int lane, float a, float b, float c, float d) {
    union { uint2 u; __half2 h[2]; } cv;
    cv.h[0] = __float22half2_rn(make_float2(a, b));
    cv.h[1] = __float22half2_rn(make_float2(c, d));
    ((uint2*)row)[lane] = cv.u;
}

// 8 halfs (uint4) * p accumulated into 8 fp32
__device__ __forceinline__ void h8_fma(float* acc, uint4 v, float p) {
    union { unsigned u; __half2 h; } c;
    float2 f;
    c.u = v.x; f = __half22float2(c.h); acc[0] += f.x * p; acc[1] += f.y * p;
    c.u = v.y; f = __half22float2(c.h); acc[2] += f.x * p; acc[3] += f.y * p;
    c.u = v.z; f = __half22float2(c.h); acc[4] += f.x * p; acc[5] += f.y * p;
    c.u = v.w; f = __half22float2(c.h); acc[6] += f.x * p; acc[7] += f.y * p;
}

__device__ __forceinline__ unsigned s2u(const void* p) {
    unsigned a;
    asm("{.reg .u64 t; cvta.to.shared.u64 t,%1; cvt.u32.u64 %0,t;}" : "=r"(a) : "l"(p));
    return a;
}

#define LDSM4(r0, r1, r2, r3, addr) \
    asm volatile("ldmatrix.sync.aligned.m8n8.x4.shared.b16 {%0,%1,%2,%3},[%4];" \
                 : "=r"(r0), "=r"(r1), "=r"(r2), "=r"(r3) : "r"(addr))
#define LDSM4T(r0, r1, r2, r3, addr) \
    asm volatile("ldmatrix.sync.aligned.m8n8.x4.trans.shared.b16 {%0,%1,%2,%3},[%4];" \
                 : "=r"(r0), "=r"(r1), "=r"(r2), "=r"(r3) : "r"(addr))
#define MMA16816(C, a0, a1, a2, a3, b0, b1) \
    asm volatile("mma.sync.aligned.m16n8k16.row.col.f32.f16.f16.f32 " \
                 "{%0,%1,%2,%3},{%4,%5,%6,%7},{%8,%9},{%0,%1,%2,%3};" \
                 : "+f"((C)[0]), "+f"((C)[1]), "+f"((C)[2]), "+f"((C)[3]) \
                 : "r"(a0), "r"(a1), "r"(a2), "r"(a3), "r"(b0), "r"(b1))

// ---------------- CSR build ----------------
__global__ void k_hist(const int* __restrict__ ei, const int* __restrict__ batch) {
    int i = blockIdx.x * blockDim.x + threadIdx.x;
    if (i < N_EDGES) atomicAdd(&g_deg[ei[N_EDGES + i]], 1);
    if (i < N_NODES) atomicAdd(&g_gdeg[batch[i]], 1);
}

__global__ void k_scan_block() {
    __shared__ int sh[1024];
    int t = threadIdx.x;
    int i = blockIdx.x * 1024 + t;
    int v = (i < N_NODES) ? g_deg[i] : 0;
    sh[t] = v;
    __syncthreads();
    for (int off = 1; off < 1024; off <<= 1) {
        int a = (t >= off) ? sh[t - off] : 0;
        __syncthreads();
        sh[t] += a;
        __syncthreads();
    }
    if (i < N_NODES) g_rowptr[i] = sh[t] - v;
    if (t == 1023) g_bsums[blockIdx.x] = sh[1023];
}

// fused: block-sum scan + add + cursor init + total; last block also builds g_gptr
__global__ void k_scan_add2(int nb) {
    __shared__ int sb[128];
    int t = threadIdx.x;
    if (t < 128) sb[t] = (t < nb) ? g_bsums[t] : 0;
    __syncthreads();
    for (int off = 1; off < 128; off <<= 1) {
        int a = (t < 128 && t >= off) ? sb[t - off] : 0;
        __syncthreads();
        if (t < 128) sb[t] += a;
        __syncthreads();
    }
    int i = blockIdx.x * blockDim.x + t;
    if (i < N_NODES) {
        int b = i >> 10;
        int vv = g_rowptr[i] + (b ? sb[b - 1] : 0);
        g_rowptr[i] = vv;
        g_cursor[i] = vv;
    }
    if (i == 0) g_rowptr[N_NODES] = sb[nb - 1];

    if (blockIdx.x == gridDim.x - 1) {    // graph-pointer scan (1024 entries, 4/thread)
        __shared__ int gs[256];
        int b4 = t * 4;
        int a0 = g_gdeg[b4], a1 = g_gdeg[b4 + 1], a2 = g_gdeg[b4 + 2], a3 = g_gdeg[b4 + 3];
        int tot = a0 + a1 + a2 + a3;
        gs[t] = tot;
        __syncthreads();
        for (int off = 1; off < 256; off <<= 1) {
            int a = (t >= off) ? gs[t - off] : 0;
            __syncthreads();
            gs[t] += a;
            __syncthreads();
        }
        int excl = gs[t] - tot;
        g_gptr[b4]     = excl;
        g_gptr[b4 + 1] = excl + a0;
        g_gptr[b4 + 2] = excl + a0 + a1;
        g_gptr[b4 + 3] = excl + a0 + a1 + a2;
        if (t == 255) g_gptr[N_GRAPH] = gs[255];
    }
}

__global__ void k_scatter(const int* __restrict__ ei) {
    int i = blockIdx.x * blockDim.x + threadIdx.x;
    if (i >= N_EDGES) return;
    int s = ei[i];
    int d = ei[N_EDGES + i];
    int pos = atomicAdd(&g_cursor[d], 1);
    g_sd[pos] = make_int2(s, d);
}

// warp-per-node sort of src keys (dst is row-constant, stays in place)
__global__ void k_rowsortw() {
    __shared__ int buf[WPB][160];
    int wl = threadIdx.x >> 5, lane = threadIdx.x & 31;
    int n = blockIdx.x * WPB + wl;
    if (n >= N_NODES) return;
    int rs = g_rowptr[n], L = g_rowptr[n + 1] - rs;
    if (L <= 1) return;
    if (L <= 32) {
        int v = (lane < L) ? g_sd[rs + lane].x : 0x7fffffff;
#pragma unroll
        for (int k = 2; k <= 32; k <<= 1) {
#pragma unroll
            for (int j = k >> 1; j; j >>= 1) {
                int o = __shfl_xor_sync(~0u, v, j);
                bool up = ((lane & k) == 0);
                bool lo = ((lane & j) == 0);
                v = (up == lo) ? min(v, o) : max(v, o);
            }
        }
        if (lane < L) g_sd[rs + lane].x = v;
    } else if (L <= 64) {
        int i0 = lane, i1 = lane + 32;
        int v0 = (i0 < L) ? g_sd[rs + i0].x : 0x7fffffff;
        int v1 = (i1 < L) ? g_sd[rs + i1].x : 0x7fffffff;
#pragma unroll
        for (int k = 2; k <= 64; k <<= 1) {
#pragma unroll
            for (int j = k >> 1; j; j >>= 1) {
                if (j >= 32) {
                    int lo = min(v0, v1), hi = max(v0, v1);
                    v0 = lo; v1 = hi;
                } else {
                    int o0 = __shfl_xor_sync(~0u, v0, j);
                    int o1 = __shfl_xor_sync(~0u, v1, j);
                    bool up0 = ((i0 & k) == 0), up1 = ((i1 & k) == 0);
                    bool lo0 = ((i0 & j) == 0), lo1 = ((i1 & j) == 0);
                    v0 = (up0 == lo0) ? min(v0, o0) : max(v0, o0);
                    v1 = (up1 == lo1) ? min(v1, o1) : max(v1, o1);
                }
            }
        }
        if (i0 < L) g_sd[rs + i0].x = v0;
        if (i1 < L) g_sd[rs + i1].x = v1;
    } else if (L <= 160) {
        for (int i = lane; i < L; i += 32) buf[wl][i] = g_sd[rs + i].x;
        __syncwarp();
        for (int p = 0; p < L; p++) {
            for (int i = (p & 1) + 2 * lane; i + 1 < L; i += 64) {
                int a = buf[wl][i], b = buf[wl][i + 1];
                if (a > b) { buf[wl][i] = b; buf[wl][i + 1] = a; }
            }
            __syncwarp();
        }
        for (int i = lane; i < L; i += 32) g_sd[rs + i].x = buf[wl][i];
    } else if (lane == 0) {
        int re = rs + L;
        for (int i = rs + 1; i < re; i++) {
            int key = g_sd[i].x;
            int j = i - 1;
            while (j >= rs && g_sd[j].x > key) { g_sd[j + 1].x = g_sd[j].x; j--; }
            g_sd[j + 1].x = key;
        }
    }
}

// ---------------- layer 1: embed + LN + W1 + logits (8 nodes/warp, f32x2) ----------------
__global__ void k_node1(const int* __restrict__ x, const float* __restrict__ emb,
                        const float* __restrict__ lng, const float* __restrict__ lnb,
                        const float* __restrict__ W1, const float* __restrict__ asr,
                        const float* __restrict__ adt) {
    __shared__ ulonglong2 sW[EMB * 32];
    __shared__ float sxn[WPB][NPW][EMB];
    int tid = threadIdx.x;
    int wl = tid >> 5, lane = tid & 31;
    {
        const ulonglong2* W4 = (const ulonglong2*)W1;
        for (int i = tid; i < EMB * 32; i += NTPB) sW[i] = W4[i];
    }
    int nbase = (blockIdx.x * WPB + wl) * NPW;

#pragma unroll
    for (int j = 0; j < NPW; j++) {
        int n = nbase + j;
        float xn = 0.f;
        if (n < N_NODES) {
            int vi = x[n];
            float xv = emb[vi * EMB + lane];
            float m = xv;
            for (int o = 16; o; o >>= 1) m += __shfl_xor_sync(~0u, m, o);
            m *= (1.f / EMB);
            float dv = xv - m;
            float var = dv * dv;
            for (int o = 16; o; o >>= 1) var += __shfl_xor_sync(~0u, var, o);
            var *= (1.f / EMB);
            xn = dv * rsqrtf(var + 1e-5f) * lng[lane] + lnb[lane];
        }
        sxn[wl][j][lane] = xn;
    }
    __syncthreads();

    unsigned long long accA[NPW], accB[NPW];
#pragma unroll
    for (int j = 0; j < NPW; j++) { accA[j] = 0ull; accB[j] = 0ull; }
#pragma unroll
    for (int k = 0; k < EMB; k += 4) {
        ulonglong2 w0 = sW[(k + 0) * 32 + lane];
        ulonglong2 w1 = sW[(k + 1) * 32 + lane];
        ulonglong2 w2 = sW[(k + 2) * 32 + lane];
        ulonglong2 w3 = sW[(k + 3) * 32 + lane];
#pragma unroll
        for (int j = 0; j < NPW; j++) {
            float4 h4 = *(const float4*)&sxn[wl][j][k];
            unsigned long long p;
            p = pack2(h4.x); fma2(accA[j], w0.x, p); fma2(accB[j], w0.y, p);
            p = pack2(h4.y); fma2(accA[j], w1.x, p); fma2(accB[j], w1.y, p);
            p = pack2(h4.z); fma2(accA[j], w2.x, p); fma2(accB[j], w2.y, p);
            p = pack2(h4.w); fma2(accA[j], w3.x, p); fma2(accB[j], w3.y, p);
        }
    }

    float4 as4 = __ldg((const float4*)asr + lane);
    float4 ad4 = __ldg((const float4*)adt + lane);
#pragma unroll
    for (int j = 0; j < NPW; j++) {
        int n = nbase + j;
        float2 lo = unpack2(accA[j]), hi = unpack2(accB[j]);
        float ps = lo.x * as4.x + lo.y * as4.y + hi.x * as4.z + hi.y * as4.w;
        float pd = lo.x * ad4.x + lo.y * ad4.y + hi.x * ad4.z + hi.y * ad4.w;
        for (int o = 8; o; o >>= 1) {
            ps += __shfl_xor_sync(~0u, ps, o);
            pd += __shfl_xor_sync(~0u, pd, o);
        }
        if (n < N_NODES) {
            store_h4(g_xwh + (size_t)n * DC, lane, lo.x, lo.y, hi.x, hi.y);
            if ((lane & 15) == 0) {
                int h = lane >> 4;
                g_als[n * 2 + h] = ps;
                g_ald[n * 2 + h] = pd;
            }
        }
    }
}

// ---------------- edge-parallel: packed {src, exp0, exp1} precompute ----------------
__global__ void k_elog() {
    int p = blockIdx.x * blockDim.x + threadIdx.x;
    if (p >= N_EDGES) return;
    int2 sd = g_sd[p];
    float2 a = __ldg((const float2*)g_als + sd.x);
    float2 b = __ldg((const float2*)g_ald + sd.y);
    uint4 rec;
    rec.x = (unsigned)sd.x;
    rec.y = __float_as_uint(__expf(lrelu(a.x + b.x, 0.2f)));
    rec.z = __float_as_uint(__expf(lrelu(a.y + b.y, 0.2f)));
    rec.w = 0;
    g_pk[p] = rec;
}

// ---------------- GAT aggregation: warp/node, register-staged packed records ----------------
__global__ void k_agg(const float* __restrict__ bias, float* __restrict__ out2, int layer) {
    int n = blockIdx.x * WPB + (threadIdx.x >> 5);
    int lane = threadIdx.x & 31;
    if (n >= N_NODES) return;

    int rs = g_rowptr[n], re = g_rowptr[n + 1];
    int L = re - rs;
    float2 a = *(const float2*)&g_als[2 * n];
    float2 b = *(const float2*)&g_ald[2 * n];
    float ps0 = __expf(lrelu(a.x + b.x, 0.2f));
    float ps1 = __expf(lrelu(a.y + b.y, 0.2f));

    int half  = lane >> 4;
    int s16   = lane & 15;
    int headb = s16 >> 3;

    float acc[8];
    {
        float pself = (half == 0) ? (headb ? ps1 : ps0) : 0.f;
        uint4 xs = __ldg((const uint4*)(g_xwh + (size_t)n * DC) + s16);
#pragma unroll
        for (int i = 0; i < 8; i++) acc[i] = 0.f;
        h8_fma(acc, xs, pself);
    }

    float s0, s1;
    if (L <= 32) {
        // stage entire row in registers: lane k owns edge rs+k (one LDG.128)
        uint4 rec_l = (lane < L) ? __ldg(g_pk + rs + lane) : make_uint4(0, 0, 0, 0);
        s0 = __uint_as_float(rec_l.y); s1 = __uint_as_float(rec_l.z);
#pragma unroll
        for (int o = 16; o; o >>= 1) {
            s0 += __shfl_xor_sync(~0u, s0, o);
            s1 += __shfl_xor_sync(~0u, s1, o);
        }
#pragma unroll 8
        for (int j = 0; j < L; j += 2) {
            int jj = (j + half) & 31;
            int srcj = __shfl_sync(~0u, (int)rec_l.x, jj);
            float px = __shfl_sync(~0u, __uint_as_float(rec_l.y), jj);
            float py = __shfl_sync(~0u, __uint_as_float(rec_l.z), jj);
            float p = (j + half < L) ? (headb ? py : px) : 0.f;
            uint4 xv = __ldg((const uint4*)(g_xwh + (size_t)srcj * DC) + s16);
            h8_fma(acc, xv, p);
        }
    } else {
        s0 = 0.f; s1 = 0.f;
        for (int k = rs + lane; k < re; k += 32) {
            uint4 rec = __ldg(g_pk + k);
            s0 += __uint_as_float(rec.y);
            s1 += __uint_as_float(rec.z);
        }
#pragma unroll
        for (int o = 16; o; o >>= 1) {
            s0 += __shfl_xor_sync(~0u, s0, o);
            s1 += __shfl_xor_sync(~0u, s1, o);
        }
#pragma unroll 8
        for (int k = rs; k < re; k += 2) {
            int kk = k + half;
            int kc = kk < re ? kk : re - 1;
            uint4 rec = __ldg(g_pk + kc);          // one broadcast LDG.128 per edge
            int src = (int)rec.x;
            float p = (kk < re) ? __uint_as_float(headb ? rec.z : rec.y) : 0.f;
            uint4 xv = __ldg((const uint4*)(g_xwh + (size_t)src * DC) + s16);
            h8_fma(acc, xv, p);
        }
    }

#pragma unroll
    for (int i = 0; i < 8; i++) acc[i] += __shfl_xor_sync(~0u, acc[i], 16);

    float inv0 = 1.f / (s0 + ps0);
    float inv1 = 1.f / (s1 + ps1);
    float invh = headb ? inv1 : inv0;
    int idx = s16 * 2 + half;
    float4 bi = __ldg((const float4*)bias + idx);
    const float* ap = acc + half * 4;
    float4 o;
    o.x = ap[0] * invh + bi.x;
    o.y = ap[1] * invh + bi.y;
    o.z = ap[2] * invh + bi.z;
    o.w = ap[3] * invh + bi.w;
    if (layer == 1) {
        o.x = lrelu(o.x, 0.05f); o.y = lrelu(o.y, 0.05f);
        o.z = lrelu(o.z, 0.05f); o.w = lrelu(o.w, 0.05f);
        store_h4(g_h1h + (size_t)n * DC, idx, o.x, o.y, o.z, o.w);   // fp16 for MMA node2
    } else {
        ((float4*)out2)[(size_t)n * 32 + idx] = o;                   // fp32 h output
        store_h4(g_h1h + (size_t)n * DC, idx, o.x, o.y, o.z, o.w);   // fp16 for gate + pool
    }
}

// ---------------- layer 2 node transform via HMMA: h1h @ W2 + logits ----------------
#define PITCH_H 136   // halfs per smem row (128 + 8 pad)
__global__ void k_node2m(const float* __restrict__ W2, const float* __restrict__ asr,
                         const float* __restrict__ adt) {
    extern __shared__ char dsm[];
    __half* sA = (__half*)dsm;                                 // 128 x PITCH_H
    __half* sB = (__half*)(dsm + 128 * PITCH_H * 2);           // 128 x PITCH_H
    float*  sAs = (float*)(dsm + 2 * 128 * PITCH_H * 2);       // 128
    float*  sAd = sAs + 128;

    int tid = threadIdx.x;
    int wl = tid >> 5, lane = tid & 31;
    int bb = blockIdx.x * 128;

    if (tid < 128) { sAs[tid] = asr[tid]; sAd[tid] = adt[tid]; }
    for (int i = tid; i < 128 * 64; i += NTPB) {
        int k = i >> 6, c2 = i & 63;
        float2 w = *(const float2*)(W2 + k * 128 + c2 * 2);
        *(__half2*)(sB + k * PITCH_H + c2 * 2) = __float22half2_rn(w);
    }
    for (int i = tid; i < 128 * 16; i += NTPB) {
        int r = i >> 4, c = i & 15;
        int rg = bb + r; if (rg >= N_NODES) rg = N_NODES - 1;
        uint4 v = *(const uint4*)(g_h1h + (size_t)rg * DC + c * 8);
        *(uint4*)(sA + r * PITCH_H + c * 8) = v;
    }
    __syncthreads();

    float C[16][4];
#pragma unroll
    for (int t = 0; t < 16; t++) { C[t][0] = 0.f; C[t][1] = 0.f; C[t][2] = 0.f; C[t][3] = 0.f; }

    int g = lane >> 3;
    int rrow = (lane & 7) + ((g & 1) << 3);
    unsigned aBase = s2u(sA + wl * 16 * PITCH_H) + rrow * (PITCH_H * 2) + ((g >> 1) << 4);
    unsigned bBase = s2u(sB) + rrow * (PITCH_H * 2) + ((g >> 1) << 4);

#pragma unroll
    for (int kg = 0; kg < 8; kg++) {
        unsigned a0, a1, a2, a3;
        LDSM4(a0, a1, a2, a3, aBase + kg * 32);
#pragma unroll
        for (int nt = 0; nt < 8; nt++) {
            unsigned b0, b1, b2, b3;
            LDSM4T(b0, b1, b2, b3, bBase + kg * 16 * (PITCH_H * 2) + nt * 32);
            MMA16816(C[nt * 2],     a0, a1, a2, a3, b0, b1);
            MMA16816(C[nt * 2 + 1], a0, a1, a2, a3, b2, b3);
        }
    }

    int q = lane & 3;
    int r0 = wl * 16 + (lane >> 2);
    int n0 = bb + r0, n1 = n0 + 8;
    float psA0 = 0.f, psB0 = 0.f, pdA0 = 0.f, pdB0 = 0.f;
    float psA1 = 0.f, psB1 = 0.f, pdA1 = 0.f, pdB1 = 0.f;
#pragma unroll
    for (int nt = 0; nt < 16; nt++) {
        int col = nt * 8 + q * 2;
        float c0 = C[nt][0], c1 = C[nt][1], c2 = C[nt][2], c3 = C[nt][3];
        if (n0 < N_NODES)
            *(__half2*)(g_xwh + (size_t)n0 * DC + col) = __floats2half2_rn(c0, c1);
        if (n1 < N_NODES)
            *(__half2*)(g_xwh + (size_t)n1 * DC + col) = __floats2half2_rn(c2, c3);
        float as0 = sAs[col], as1 = sAs[col + 1];
        float ad0 = sAd[col], ad1 = sAd[col + 1];
        float s_r0 = c0 * as0 + c1 * as1, d_r0 = c0 * ad0 + c1 * ad1;
        float s_r1 = c2 * as0 + c3 * as1, d_r1 = c2 * ad0 + c3 * ad1;
        if (nt < 8) { psA0 += s_r0; pdA0 += d_r0; psA1 += s_r1; pdA1 += d_r1; }
        else        { psB0 += s_r0; pdB0 += d_r0; psB1 += s_r1; pdB1 += d_r1; }
    }
#pragma unroll
    for (int o = 1; o <= 2; o <<= 1) {
        psA0 += __shfl_xor_sync(~0u, psA0, o); psB0 += __shfl_xor_sync(~0u, psB0, o);
        pdA0 += __shfl_xor_sync(~0u, pdA0, o); pdB0 += __shfl_xor_sync(~0u, pdB0, o);
        psA1 += __shfl_xor_sync(~0u, psA1, o); psB1 += __shfl_xor_sync(~0u, psB1, o);
        pdA1 += __shfl_xor_sync(~0u, pdA1, o); pdB1 += __shfl_xor_sync(~0u, pdB1, o);
    }
    if (q == 0) {
        if (n0 < N_NODES) {
            g_als[2 * n0] = psA0; g_als[2 * n0 + 1] = psB0;
            g_ald[2 * n0] = pdA0; g_ald[2 * n0 + 1] = pdB0;
        }
        if (n1 < N_NODES) {
            g_als[2 * n1] = psA1; g_als[2 * n1 + 1] = psB1;
            g_ald[2 * n1] = pdA1; g_ald[2 * n1 + 1] = pdB1;
        }
    }
}

// ---------------- gate MLP via HMMA: h(fp16) @ gw1 -> lrelu -> @ gw2 ----------------
#define PB_G 72   // halfs per smem row for gw1 tile (64 + 8 pad)
__global__ void k_gatem(const float* __restrict__ gw1, const float* __restrict__ gb1,
                        const float* __restrict__ gw2, const float* __restrict__ gb2) {
    extern __shared__ char dsm[];
    __half* sA = (__half*)dsm;                                 // 128 x PITCH_H (h rows)
    __half* sB = (__half*)(dsm + 128 * PITCH_H * 2);           // 128 x PB_G (gw1)
    float*  sGb = (float*)(dsm + 128 * PITCH_H * 2 + 128 * PB_G * 2);  // 64
    float*  sGw = sGb + 64;                                    // 64

    int tid = threadIdx.x;
    int wl = tid >> 5, lane = tid & 31;
    int bb = blockIdx.x * 128;

    if (tid < 64) { sGb[tid] = gb1[tid]; sGw[tid] = gw2[tid]; }
    for (int i = tid; i < 128 * 32; i += NTPB) {
        int k = i >> 5, c2 = i & 31;
        float2 w = *(const float2*)(gw1 + k * 64 + c2 * 2);
        *(__half2*)(sB + k * PB_G + c2 * 2) = __float22half2_rn(w);
    }
    for (int i = tid; i < 128 * 16; i += NTPB) {
        int r = i >> 4, c = i & 15;
        int rg = bb + r; if (rg >= N_NODES) rg = N_NODES - 1;
        uint4 v = *(const uint4*)(g_h1h + (size_t)rg * DC + c * 8);
        *(uint4*)(sA + r * PITCH_H + c * 8) = v;
    }
    __syncthreads();

    float C[8][4];
#pragma unroll
    for (int t = 0; t < 8; t++) { C[t][0] = 0.f; C[t][1] = 0.f; C[t][2] = 0.f; C[t][3] = 0.f; }

    int g = lane >> 3;
    int rrow = (lane & 7) + ((g & 1) << 3);
    unsigned aBase = s2u(sA + wl * 16 * PITCH_H) + rrow * (PITCH_H * 2) + ((g >> 1) << 4);
    unsigned bBase = s2u(sB) + rrow * (PB_G * 2) + ((g >> 1) << 4);

#pragma unroll
    for (int kg = 0; kg < 8; kg++) {
        unsigned a0, a1, a2, a3;
        LDSM4(a0, a1, a2, a3, aBase + kg * 32);
#pragma unroll
        for (int nt = 0; nt < 4; nt++) {
            unsigned b0, b1, b2, b3;
            LDSM4T(b0, b1, b2, b3, bBase + kg * 16 * (PB_G * 2) + nt * 32);
            MMA16816(C[nt * 2],     a0, a1, a2, a3, b0, b1);
            MMA16816(C[nt * 2 + 1], a0, a1, a2, a3, b2, b3);
        }
    }

    int q = lane & 3;
    int r0 = wl * 16 + (lane >> 2);
    int n0 = bb + r0, n1 = n0 + 8;
    float g0 = 0.f, g1 = 0.f;
#pragma unroll
    for (int nt = 0; nt < 8; nt++) {
        int col = nt * 8 + q * 2;
        float b0 = sGb[col], b1 = sGb[col + 1];
        float w0 = sGw[col], w1 = sGw[col + 1];
        g0 += lrelu(C[nt][0] + b0, 0.05f) * w0 + lrelu(C[nt][1] + b1, 0.05f) * w1;
        g1 += lrelu(C[nt][2] + b0, 0.05f) * w0 + lrelu(C[nt][3] + b1, 0.05f) * w1;
    }
#pragma unroll
    for (int o = 1; o <= 2; o <<= 1) {
        g0 += __shfl_xor_sync(~0u, g0, o);
        g1 += __shfl_xor_sync(~0u, g1, o);
    }
    if (q == 0) {
        float gbias = *gb2;
        if (n0 < N_NODES) g_gate[n0] = g0 + gbias;
        if (n1 < N_NODES) g_gate[n1] = g1 + gbias;
    }
}

// ---------------- per-graph softmax pooling (fp16 h) + scratch re-zero ----------------
__global__ void k_pool(float* __restrict__ zout) {
    int g = blockIdx.x;
    int t = threadIdx.x;
    int s = g_gptr[g], e = g_gptr[g + 1];
    __shared__ float red[128];
    __shared__ float wbuf[128];

    float lm = -3.4e38f;
    for (int i = s + t; i < e; i += 128) lm = fmaxf(lm, g_gate[i]);
    red[t] = lm;
    __syncthreads();
    for (int o = 64; o; o >>= 1) { if (t < o) red[t] = fmaxf(red[t], red[t + o]); __syncthreads(); }
    float gm = red[0];
    __syncthreads();

    float ls = 0.f;
    for (int i = s + t; i < e; i += 128) ls += __expf(g_gate[i] - gm);
    red[t] = ls;
    __syncthreads();
    for (int o = 64; o; o >>= 1) { if (t < o) red[t] += red[t + o]; __syncthreads(); }
    float inv = (e > s) ? 1.f / red[0] : 0.f;
    __syncthreads();

    float acc = 0.f;
    for (int base = s; base < e; base += 128) {
        int i = base + t;
        wbuf[t] = (i < e) ? __expf(g_gate[i] - gm) * inv : 0.f;
        __syncthreads();
        int cnt = min(128, e - base);
#pragma unroll 4
        for (int j = 0; j < cnt; j++)
            acc += wbuf[j] * __half2float(g_h1h[(size_t)(base + j) * DC + t]);
        __syncthreads();
    }
    zout[g * DC + t] = acc;

    // re-zero histogram scratch for the next kernel_launch call (1024*128 >= N_NODES)
    int gid = g * 128 + t;
    if (gid < N_NODES) g_deg[gid] = 0;
    if (gid < N_GRAPH) g_gdeg[gid] = 0;
}

// ---------------- launch ----------------
extern "C" void kernel_launch(void* const* d_in, const int* in_sizes, int n_in,
                              void* d_out, int out_size) {
    const int*   x     = (const int*)d_in[0];
    const int*   ei    = (const int*)d_in[1];
    const int*   batch = (const int*)d_in[2];
    const float* emb   = (const float*)d_in[3];
    const float* lng   = (const float*)d_in[4];
    const float* lnb   = (const float*)d_in[5];
    const float* W1    = (const float*)d_in[6];
    const float* as1   = (const float*)d_in[7];
    const float* ad1   = (const float*)d_in[8];
    const float* b1    = (const float*)d_in[9];
    const float* W2    = (const float*)d_in[10];
    const float* as2   = (const float*)d_in[11];
    const float* ad2   = (const float*)d_in[12];
    const float* b2    = (const float*)d_in[13];
    const float* gw1   = (const float*)d_in[14];
    const float* gb1   = (const float*)d_in[15];
    const float* gw2   = (const float*)d_in[16];
    const float* gb2   = (const float*)d_in[17];
    float* out  = (float*)d_out;
    float* zout = out + (size_t)N_NODES * DC;

    const int node2_smem = 2 * 128 * PITCH_H * 2 + 2 * 128 * 4;               // ~70.7 KB
    const int gate_smem  = 128 * PITCH_H * 2 + 128 * PB_G * 2 + 2 * 64 * 4;   // ~53.8 KB
    cudaFuncSetAttribute(k_node2m, cudaFuncAttributeMaxDynamicSharedMemorySize, node2_smem);
    cudaFuncSetAttribute(k_gatem,  cudaFuncAttributeMaxDynamicSharedMemorySize, gate_smem);

    int nb_scan = (N_NODES + 1023) / 1024;

    // CSR build + graph segment pointers
    k_hist<<<(N_EDGES + 255) / 256, 256>>>(ei, batch);
    k_scan_block<<<nb_scan, 1024>>>();
    k_scan_add2<<<(N_NODES + 255) / 256, 256>>>(nb_scan);
    k_scatter<<<(N_EDGES + 255) / 256, 256>>>(ei);
    k_rowsortw<<<(N_NODES + WPB - 1) / WPB, NTPB>>>();

    int nb_agg  = (N_NODES + WPB - 1) / WPB;
    int nb_blk  = (N_NODES + WPB * NPW - 1) / (WPB * NPW);
    int nb_edge = (N_EDGES + 255) / 256;
    int nb_mma  = (N_NODES + 127) / 128;

    k_node1<<<nb_blk, NTPB>>>(x, emb, lng, lnb, W1, as1, ad1);
    k_elog<<<nb_edge, 256>>>();
    k_agg<<<nb_agg, NTPB>>>(b1, nullptr, 1);
    k_node2m<<<nb_mma, NTPB, node2_smem>>>(W2, as2, ad2);
    k_elog<<<nb_edge, 256>>>();
    k_agg<<<nb_agg, NTPB>>>(b2, out, 2);
    k_gatem<<<nb_mma, NTPB, gate_smem>>>(gw1, gb1, gw2, gb2);
    k_pool<<<N_GRAPH, 128>>>(zout);
}